// round 10
// baseline (speedup 1.0000x reference)
#include <cuda_runtime.h>
#include <cuda_fp16.h>
#include <math.h>

#define NSIDE 512
#define NPIX  (512*512)
#define NF    257

typedef __half2 h2;

// ---- scratch ----
__device__ __align__(16) h2     g_tmpR[NF * NPIX / 2];  // re plane, [f][q][y], fp16 x-pairs
__device__ __align__(16) h2     g_tmpI[NF * NPIX / 2];  // im plane
__device__ __align__(16) __half g_m[NF * NPIX];         // modulus*512, [f][q][y][parity]
__device__ float g_gram[32 * 16 * 24];
__device__ float g_a2;
__device__ uint2 g_twh[512];                            // fp16 twiddles {(c,c),(s,s)}

__device__ __forceinline__ unsigned h2u(h2 a){ return *reinterpret_cast<unsigned*>(&a); }
__device__ __forceinline__ h2 u2h(unsigned a){ return *reinterpret_cast<h2*>(&a); }

#define DECL_H_CONSTS \
  const h2 CC = __floats2half2_rn(0.70710678118654752440f, 0.70710678118654752440f); \
  const h2 NC = __floats2half2_rn(-0.70710678118654752440f, -0.70710678118654752440f);

// 8-pt DFT, +i sign, natural order, fp16 SoA (2 pixels per op, zero swaps)
__device__ __forceinline__ void fft8h(h2 R[8], h2 I[8], h2 CC, h2 NC) {
  h2 es0R=__hadd2(R[0],R[4]), es0I=__hadd2(I[0],I[4]);
  h2 ed0R=__hsub2(R[0],R[4]), ed0I=__hsub2(I[0],I[4]);
  h2 es1R=__hadd2(R[2],R[6]), es1I=__hadd2(I[2],I[6]);
  h2 ed1R=__hsub2(R[2],R[6]), ed1I=__hsub2(I[2],I[6]);
  h2 E0R=__hadd2(es0R,es1R), E0I=__hadd2(es0I,es1I);
  h2 E2R=__hsub2(es0R,es1R), E2I=__hsub2(es0I,es1I);
  h2 E1R=__hsub2(ed0R,ed1I), E1I=__hadd2(ed0I,ed1R);   // ed0 + i*ed1
  h2 E3R=__hadd2(ed0R,ed1I), E3I=__hsub2(ed0I,ed1R);   // ed0 - i*ed1
  h2 os0R=__hadd2(R[1],R[5]), os0I=__hadd2(I[1],I[5]);
  h2 od0R=__hsub2(R[1],R[5]), od0I=__hsub2(I[1],I[5]);
  h2 os1R=__hadd2(R[3],R[7]), os1I=__hadd2(I[3],I[7]);
  h2 od1R=__hsub2(R[3],R[7]), od1I=__hsub2(I[3],I[7]);
  h2 O0R=__hadd2(os0R,os1R), O0I=__hadd2(os0I,os1I);
  h2 O2R=__hsub2(os0R,os1R), O2I=__hsub2(os0I,os1I);
  h2 O1R=__hsub2(od0R,od1I), O1I=__hadd2(od0I,od1R);
  h2 O3R=__hadd2(od0R,od1I), O3I=__hsub2(od0I,od1R);
  h2 O1tR=__hmul2(__hsub2(O1R,O1I), CC);
  h2 O1tI=__hmul2(__hadd2(O1R,O1I), CC);
  h2 O3tR=__hmul2(__hadd2(O3R,O3I), NC);   // -C(x+y)
  h2 O3tI=__hmul2(__hsub2(O3R,O3I), CC);   // C(x-y)
  R[0]=__hadd2(E0R,O0R);  I[0]=__hadd2(E0I,O0I);
  R[4]=__hsub2(E0R,O0R);  I[4]=__hsub2(E0I,O0I);
  R[1]=__hadd2(E1R,O1tR); I[1]=__hadd2(E1I,O1tI);
  R[5]=__hsub2(E1R,O1tR); I[5]=__hsub2(E1I,O1tI);
  R[2]=__hsub2(E2R,O2I);  I[2]=__hadd2(E2I,O2R);       // E2 + i*O2
  R[6]=__hadd2(E2R,O2I);  I[6]=__hsub2(E2I,O2R);       // E2 - i*O2
  R[3]=__hadd2(E3R,O3tR); I[3]=__hadd2(E3I,O3tI);
  R[7]=__hsub2(E3R,O3tR); I[7]=__hsub2(E3I,O3tI);
}

__device__ __forceinline__ void ctwh(h2& R, h2& I, uint2 w) {   // *(c + i s)
  h2 wc = u2h(w.x), ws = u2h(w.y), nws = u2h(w.y ^ 0x80008000u);
  h2 r = __hfma2(I, nws, __hmul2(R, wc));
  h2 i = __hfma2(R, ws,  __hmul2(I, wc));
  R = r; I = i;
}

// 8x8 transpose among 8 lanes differing in low-3 lane bits (32-bit shuffles)
__device__ __forceinline__ void transpose8h(h2 v[8], int f3) {
#pragma unroll
  for (int mb = 0; mb < 3; mb++) {
    const int m = 1 << mb;
#pragma unroll
    for (int i = 0; i < 8; i++) {
      if ((i & m) == 0) {
        const int ip = i | m;
        const bool hi = (f3 & m) != 0;
        unsigned send = h2u(hi ? v[i] : v[ip]);
        unsigned got = __shfl_xor_sync(0xffffffffu, send, m);
        if (hi) v[i] = u2h(got); else v[ip] = u2h(got);
      }
    }
  }
}

__global__ void init_kernel() {
  int t = threadIdx.x;
  for (int m = t; m < 512; m += 256) {
    float s, c;
    sincospif((float)m * (1.0f / 256.0f), &s, &c);
    h2 wc = __floats2half2_rn(c, c), ws = __floats2half2_rn(s, s);
    g_twh[m] = make_uint2(h2u(wc), h2u(ws));
  }
  for (int i = t; i < 32 * 384; i += 256) g_gram[i] = 0.f;
  if (t == 0) g_a2 = 0.f;
}

// ---- stage 1: float4-staged product + 512-pt IFFT along x (fp16 SoA); repack to x-pairs ----
__global__ void __launch_bounds__(256) rows_kernel(const float2* __restrict__ xh2,
                                                   const float* __restrict__ pre,
                                                   const float* __restrict__ pim) {
  __shared__ __half stR[8 * 512], stI[8 * 512];   // 16 KB staging: product planes [row][x]
  __shared__ h2 SR[2304], SI[2304];               // 18 KB: exchange + final repack
  DECL_H_CONSTS
  const int tid = threadIdx.x;
  const int f = blockIdx.y;
  const int y0 = blockIdx.x << 3;
  const size_t fb = (size_t)f * NPIX;

  // --- stage A: wide loads + product -> smem fp16 planes ---
#pragma unroll
  for (int i = 0; i < 4; i++) {
    int idx = tid + (i << 8);           // 0..1023
    int row = idx >> 7;                 // 0..7
    int xq  = idx & 127;                // float4 index within row
    size_t ro = (size_t)(y0 + row) * NSIDE;
    float4 pr = __ldcs((const float4*)(pre + fb + ro) + xq);
    float4 pi_ = __ldcs((const float4*)(pim + fb + ro) + xq);
    float4 xa = ((const float4*)(xh2 + ro))[2 * xq];
    float4 xb = ((const float4*)(xh2 + ro))[2 * xq + 1];
    h2 r0 = __floats2half2_rn(xa.x * pr.x - xa.y * pi_.x, xa.z * pr.y - xa.w * pi_.y);
    h2 r1 = __floats2half2_rn(xb.x * pr.z - xb.y * pi_.z, xb.z * pr.w - xb.w * pi_.w);
    h2 i0 = __floats2half2_rn(xa.x * pi_.x + xa.y * pr.x, xa.z * pi_.y + xa.w * pr.y);
    h2 i1 = __floats2half2_rn(xb.x * pi_.z + xb.y * pr.z, xb.z * pi_.w + xb.w * pr.w);
    *(uint2*)&stR[(row << 9) + (xq << 2)] = make_uint2(h2u(r0), h2u(r1));
    *(uint2*)&stI[(row << 9) + (xq << 2)] = make_uint2(h2u(i0), h2u(i1));
  }
  __syncthreads();

  // --- stage B: FFT over x, y-pair SoA ---
  const int p = tid >> 6, t = tid & 63;
  h2 R[8], I[8];
#pragma unroll
  for (int q = 0; q < 8; q++) {
    int x = t + (q << 6);
    R[q] = __halves2half2(stR[(2 * p << 9) + x], stR[((2 * p + 1) << 9) + x]);
    I[q] = __halves2half2(stI[(2 * p << 9) + x], stI[((2 * p + 1) << 9) + x]);
  }
  fft8h(R, I, CC, NC);
  h2 *SRr = SR + p * 576, *SIr = SI + p * 576;
  SRr[t] = R[0]; SIr[t] = I[0];
#pragma unroll
  for (int r = 1; r < 8; r++) {
    ctwh(R[r], I[r], g_twh[t * r]);
    SRr[r * 72 + t] = R[r]; SIr[r * 72 + t] = I[r];
  }
  __syncthreads();

  const int r = t >> 3, T = t & 7;
#pragma unroll
  for (int q = 0; q < 8; q++) {
    R[q] = SRr[r * 72 + T + (q << 3)];
    I[q] = SIr[r * 72 + T + (q << 3)];
  }
  fft8h(R, I, CC, NC);
#pragma unroll
  for (int rp = 1; rp < 8; rp++) ctwh(R[rp], I[rp], g_twh[8 * T * rp]);
  transpose8h(R, T);
  transpose8h(I, T);
  fft8h(R, I, CC, NC);
  __syncthreads();

  // final: [p][x] planes (h2 = y-pair), then repack to x-pairs per y
#pragma unroll
  for (int k3 = 0; k3 < 8; k3++) {
    int x = (k3 << 6) + t;
    SR[p * 512 + x] = R[k3];
    SI[p * 512 + x] = I[k3];
  }
  __syncthreads();

  {
    const int q = tid;   // x-pair index 0..255
    unsigned hR[8], hI[8];
#pragma unroll
    for (int pp = 0; pp < 4; pp++) {
      uint2 ra = *(const uint2*)&SR[pp * 512 + 2 * q];
      uint2 ia = *(const uint2*)&SI[pp * 512 + 2 * q];
      hR[2*pp]   = __byte_perm(ra.x, ra.y, 0x5410);
      hR[2*pp+1] = __byte_perm(ra.x, ra.y, 0x7632);
      hI[2*pp]   = __byte_perm(ia.x, ia.y, 0x5410);
      hI[2*pp+1] = __byte_perm(ia.x, ia.y, 0x7632);
    }
    size_t base = ((size_t)f * 256 + q) * 512 + y0;
    uint4* dR = reinterpret_cast<uint4*>(g_tmpR + base);
    dR[0] = make_uint4(hR[0], hR[1], hR[2], hR[3]);
    dR[1] = make_uint4(hR[4], hR[5], hR[6], hR[7]);
    uint4* dI = reinterpret_cast<uint4*>(g_tmpI + base);
    dI[0] = make_uint4(hI[0], hI[1], hI[2], hI[3]);
    dI[1] = make_uint4(hI[4], hI[5], hI[6], hI[7]);
  }
}

// ---- stage 2: uint4-staged 512-pt IFFT along y + fp32 modulus ----
__global__ void __launch_bounds__(256) cols_kernel() {
  __shared__ h2 stgR[2048], stgI[2048];   // 16 KB staging: [cc][y]
  __shared__ h2 SR[2304], SI[2304];
  __shared__ float red[8];
  DECL_H_CONSTS
  const int tid = threadIdx.x;
  const int f = blockIdx.y;
  const size_t fbase = ((size_t)f * 256 + (blockIdx.x << 2)) * 512;

  // --- stage A: wide loads of 4 columns x 2 planes ---
#pragma unroll
  for (int i = 0; i < 2; i++) {
    int idx = tid + (i << 8);           // 0..511
    int off4 = idx << 2;                // h2 offset (4 per thread-step)
    *(uint4*)&stgR[off4] = __ldcs((const uint4*)(g_tmpR + fbase) + idx);
    *(uint4*)&stgI[off4] = __ldcs((const uint4*)(g_tmpI + fbase) + idx);
  }
  __syncthreads();

  const int cc = tid >> 6, t = tid & 63;
  const size_t base = fbase + (size_t)cc * 512;

  h2 R[8], I[8];
#pragma unroll
  for (int k = 0; k < 8; k++) {
    R[k] = stgR[(cc << 9) + t + (k << 6)];
    I[k] = stgI[(cc << 9) + t + (k << 6)];
  }
  fft8h(R, I, CC, NC);
  h2 *SRr = SR + cc * 576, *SIr = SI + cc * 576;
  SRr[t] = R[0]; SIr[t] = I[0];
#pragma unroll
  for (int r = 1; r < 8; r++) {
    ctwh(R[r], I[r], g_twh[t * r]);
    SRr[r * 72 + t] = R[r]; SIr[r * 72 + t] = I[r];
  }
  __syncthreads();

  const int r = t >> 3, T = t & 7;
#pragma unroll
  for (int k = 0; k < 8; k++) {
    R[k] = SRr[r * 72 + T + (k << 3)];
    I[k] = SIr[r * 72 + T + (k << 3)];
  }
  fft8h(R, I, CC, NC);
#pragma unroll
  for (int rp = 1; rp < 8; rp++) ctwh(R[rp], I[rp], g_twh[8 * T * rp]);
  transpose8h(R, T);
  transpose8h(I, T);
  fft8h(R, I, CC, NC);

  // modulus in fp32: stored h = 512*m_true
  const float SC2 = 3.814697265625e-6f, EPS = 2.62144e-3f;
  float a2loc = 0.f;
#pragma unroll
  for (int k3 = 0; k3 < 8; k3++) {
    float2 rr = __half22float2(R[k3]), ii = __half22float2(I[k3]);
    float m0 = sqrtf((rr.x * rr.x + ii.x * ii.x) * SC2 + EPS);
    float m1 = sqrtf((rr.y * rr.y + ii.y * ii.y) * SC2 + EPS);
    if (f == 0) a2loc += m0 * m0 + m1 * m1;
    ((h2*)g_m)[base + (k3 << 6) + t] = __floats2half2_rn(m0, m1);
  }
  if (f == 0) {
    int lane = tid & 31, wp = tid >> 5;
    a2loc += __shfl_down_sync(0xffffffffu, a2loc, 16);
    a2loc += __shfl_down_sync(0xffffffffu, a2loc, 8);
    a2loc += __shfl_down_sync(0xffffffffu, a2loc, 4);
    a2loc += __shfl_down_sync(0xffffffffu, a2loc, 2);
    a2loc += __shfl_down_sync(0xffffffffu, a2loc, 1);
    if (lane == 0) red[wp] = a2loc;
    __syncthreads();
    if (tid == 0) {
      float s = 0.f;
#pragma unroll
      for (int w2 = 0; w2 < 8; w2++) s += red[w2];
      atomicAdd(&g_a2, s);
    }
  }
}

// ---- stage 3: all grams via HMMA, double-buffered pipeline (unchanged) ----
#define SB 1040

__device__ __forceinline__ void mma16816(float c[4], unsigned a0, unsigned a1, unsigned a2,
                                         unsigned a3, unsigned b0, unsigned b1) {
  asm volatile("mma.sync.aligned.m16n8k16.row.col.f32.f16.f16.f32 "
               "{%0,%1,%2,%3}, {%4,%5,%6,%7}, {%8,%9}, {%0,%1,%2,%3};"
               : "+f"(c[0]), "+f"(c[1]), "+f"(c[2]), "+f"(c[3])
               : "r"(a0), "r"(a1), "r"(a2), "r"(a3), "r"(b0), "r"(b1));
}

__global__ void __launch_bounds__(256) gram_kernel() {
  __shared__ __align__(16) unsigned char sm[2][24 * SB];
  const int g = blockIdx.x;
  const int tid = threadIdx.x;
  const int w = tid >> 5, lane = tid & 31;
  const bool jg = (g < 16);
  const size_t chunkbase = (size_t)blockIdx.y * 8192;

  for (int i = tid; i < 7 * 65; i += 256) {
    ((uint4*)(sm[0] + 17 * SB))[i] = make_uint4(0, 0, 0, 0);
    ((uint4*)(sm[1] + 17 * SB))[i] = make_uint4(0, 0, 0, 0);
  }

  const int ccc = tid & 63, rbase = tid >> 6;
  const uint4* src[5];
#pragma unroll
  for (int p = 0; p < 4; p++) {
    int rr = rbase + 4 * p;
    int fidx = jg ? (1 + rr * 16 + g) : (1 + (g - 16) * 16 + rr);
    src[p] = (const uint4*)(g_m + (size_t)fidx * NPIX) + ccc;
  }
  src[4] = (const uint4*)g_m + tid;
  const bool do_lp = jg && (tid < 64);

  float c0[4] = {0,0,0,0}, c1[4] = {0,0,0,0}, c2[4] = {0,0,0,0};

  unsigned smb[2] = { (unsigned)__cvta_generic_to_shared(sm[0]),
                      (unsigned)__cvta_generic_to_shared(sm[1]) };
  const unsigned arel = ((lane & 7) + ((lane >> 3) & 1) * 8) * SB + (lane >> 4) * 16;
  const unsigned lrel = (16 + (lane & 7)) * SB + ((lane >> 3) & 1) * 16;
  const unsigned pwarp = w * 128;
  const unsigned dst0 = rbase * SB + ccc * 16;

  uint4 rg[5];
  {
    const size_t P4 = chunkbase >> 3;
#pragma unroll
    for (int p = 0; p < 4; p++) rg[p] = src[p][P4];
    if (do_lp) rg[4] = src[4][P4];
#pragma unroll
    for (int p = 0; p < 4; p++)
      *(uint4*)(sm[0] + dst0 + p * 4 * SB) = rg[p];
    if (do_lp) *(uint4*)(sm[0] + 16 * SB + tid * 16) = rg[4];
  }
  __syncthreads();

  for (int it = 0; it < 16; it++) {
    const int b = it & 1;
    if (it < 15) {
      const size_t P4 = (chunkbase + (it + 1) * 512) >> 3;
#pragma unroll
      for (int p = 0; p < 4; p++) rg[p] = src[p][P4];
      if (do_lp) rg[4] = src[4][P4];
    }

#pragma unroll
    for (int ks = 0; ks < 4; ks++) {
      unsigned pb = pwarp + ks * 32;
      unsigned a0, a1, a2, a3;
      asm volatile("ldmatrix.sync.aligned.m8n8.x4.shared.b16 {%0,%1,%2,%3}, [%4];"
                   : "=r"(a0), "=r"(a1), "=r"(a2), "=r"(a3) : "r"(smb[b] + arel + pb));
      mma16816(c0, a0, a1, a2, a3, a0, a2);
      mma16816(c1, a0, a1, a2, a3, a1, a3);
      if (jg) {
        unsigned l0, l1;
        asm volatile("ldmatrix.sync.aligned.m8n8.x2.shared.b16 {%0,%1}, [%2];"
                     : "=r"(l0), "=r"(l1) : "r"(smb[b] + lrel + pb));
        mma16816(c2, a0, a1, a2, a3, l0, l1);
      }
    }

    if (it < 15) {
      unsigned char* dbuf = sm[1 - b];
#pragma unroll
      for (int p = 0; p < 4; p++)
        *(uint4*)(dbuf + dst0 + p * 4 * SB) = rg[p];
      if (do_lp) *(uint4*)(dbuf + 16 * SB + tid * 16) = rg[4];
    }
    __syncthreads();
  }

  float* Gs = (float*)sm;
  const int row0 = lane >> 2, colb = 2 * (lane & 3);
  float* W = Gs + w * 384;
  W[row0 * 24 + colb]            = c0[0];
  W[row0 * 24 + colb + 1]        = c0[1];
  W[(row0 + 8) * 24 + colb]      = c0[2];
  W[(row0 + 8) * 24 + colb + 1]  = c0[3];
  W[row0 * 24 + 8 + colb]        = c1[0];
  W[row0 * 24 + 8 + colb + 1]    = c1[1];
  W[(row0 + 8) * 24 + 8 + colb]     = c1[2];
  W[(row0 + 8) * 24 + 8 + colb + 1] = c1[3];
  W[row0 * 24 + 16 + colb]       = c2[0];
  W[row0 * 24 + 16 + colb + 1]   = c2[1];
  W[(row0 + 8) * 24 + 16 + colb]     = c2[2];
  W[(row0 + 8) * 24 + 16 + colb + 1] = c2[3];
  __syncthreads();
  for (int e = tid; e < 384; e += 256) {
    float s = 0.f;
#pragma unroll
    for (int w2 = 0; w2 < 8; w2++) s += Gs[w2 * 384 + e];
    atomicAdd(&g_gram[g * 384 + e], s);
  }
}

// ---- stage 4: assemble (reference ordering); scale 1/(NPIX*512^2) ----
__global__ void assemble_kernel(float* __restrict__ out) {
  const int t = threadIdx.x;
  const float inv = 1.0f / ((float)NPIX * 262144.0f);
  if (t == 0) out[0] = g_a2 * inv;
  if (t >= 256) return;
  int i = t >> 4, j = t & 15;
  int rowsum = 152 * i + 16 * (15 * i - (i * (i - 1)) / 2);
  int segsum = 2 * j + ((i < 15) ? (15 - i) * j : 0) + 15 * j - (j * (j - 1)) / 2;
  int pos = 1 + rowsum + segsum;
  const float* GA = g_gram + (j * 16 + i) * 24;
  out[pos++] = GA[i] * inv;
  out[pos++] = GA[16] * inv;
  if (i < 15)
    for (int l = i + 1; l < 16; l++)
      out[pos++] = g_gram[(j * 16 + i) * 24 + l] * inv;
  if (j < 15)
    for (int l = j + 1; l < 16; l++)
      out[pos++] = g_gram[((16 + i) * 16 + j) * 24 + l] * inv;
}

extern "C" void kernel_launch(void* const* d_in, const int* in_sizes, int n_in,
                              void* d_out, int out_size) {
  const float2* xh2 = (const float2*)d_in[0];
  const float* pre  = (const float*)d_in[1];
  const float* pim  = (const float*)d_in[2];
  float* out = (float*)d_out;

  init_kernel<<<1, 256>>>();
  rows_kernel<<<dim3(NSIDE / 8, NF), 256>>>(xh2, pre, pim);
  cols_kernel<<<dim3(64, NF), 256>>>();
  gram_kernel<<<dim3(32, 32), 256>>>();
  assemble_kernel<<<1, 256>>>(out);
}

// round 11
// speedup vs baseline: 1.5976x; 1.5976x over previous
#include <cuda_runtime.h>
#include <cuda_fp16.h>
#include <math.h>

#define NSIDE 512
#define NPIX  (512*512)
#define NF    257

typedef __half2 h2;

// ---- scratch ----
__device__ __align__(16) h2     g_tmpR[NF * NPIX / 2];  // re plane, [f][q][y], fp16 x-pairs
__device__ __align__(16) h2     g_tmpI[NF * NPIX / 2];  // im plane
__device__ __align__(16) __half g_m[NF * NPIX];         // modulus*512, [f][q][y][parity]
__device__ float g_gram[32 * 16 * 24];
__device__ float g_a2;
__device__ uint2 g_twh[512];                            // fp16 twiddles {(c,c),(s,s)}

__device__ __forceinline__ unsigned h2u(h2 a){ return *reinterpret_cast<unsigned*>(&a); }
__device__ __forceinline__ h2 u2h(unsigned a){ return *reinterpret_cast<h2*>(&a); }

#define DECL_H_CONSTS \
  const h2 CC = __floats2half2_rn(0.70710678118654752440f, 0.70710678118654752440f); \
  const h2 NC = __floats2half2_rn(-0.70710678118654752440f, -0.70710678118654752440f);

// 8-pt DFT, +i sign, natural order, fp16 SoA (2 pixels per op, zero swaps)
__device__ __forceinline__ void fft8h(h2 R[8], h2 I[8], h2 CC, h2 NC) {
  h2 es0R=__hadd2(R[0],R[4]), es0I=__hadd2(I[0],I[4]);
  h2 ed0R=__hsub2(R[0],R[4]), ed0I=__hsub2(I[0],I[4]);
  h2 es1R=__hadd2(R[2],R[6]), es1I=__hadd2(I[2],I[6]);
  h2 ed1R=__hsub2(R[2],R[6]), ed1I=__hsub2(I[2],I[6]);
  h2 E0R=__hadd2(es0R,es1R), E0I=__hadd2(es0I,es1I);
  h2 E2R=__hsub2(es0R,es1R), E2I=__hsub2(es0I,es1I);
  h2 E1R=__hsub2(ed0R,ed1I), E1I=__hadd2(ed0I,ed1R);   // ed0 + i*ed1
  h2 E3R=__hadd2(ed0R,ed1I), E3I=__hsub2(ed0I,ed1R);   // ed0 - i*ed1
  h2 os0R=__hadd2(R[1],R[5]), os0I=__hadd2(I[1],I[5]);
  h2 od0R=__hsub2(R[1],R[5]), od0I=__hsub2(I[1],I[5]);
  h2 os1R=__hadd2(R[3],R[7]), os1I=__hadd2(I[3],I[7]);
  h2 od1R=__hsub2(R[3],R[7]), od1I=__hsub2(I[3],I[7]);
  h2 O0R=__hadd2(os0R,os1R), O0I=__hadd2(os0I,os1I);
  h2 O2R=__hsub2(os0R,os1R), O2I=__hsub2(os0I,os1I);
  h2 O1R=__hsub2(od0R,od1I), O1I=__hadd2(od0I,od1R);
  h2 O3R=__hadd2(od0R,od1I), O3I=__hsub2(od0I,od1R);
  h2 O1tR=__hmul2(__hsub2(O1R,O1I), CC);
  h2 O1tI=__hmul2(__hadd2(O1R,O1I), CC);
  h2 O3tR=__hmul2(__hadd2(O3R,O3I), NC);   // -C(x+y)
  h2 O3tI=__hmul2(__hsub2(O3R,O3I), CC);   // C(x-y)
  R[0]=__hadd2(E0R,O0R);  I[0]=__hadd2(E0I,O0I);
  R[4]=__hsub2(E0R,O0R);  I[4]=__hsub2(E0I,O0I);
  R[1]=__hadd2(E1R,O1tR); I[1]=__hadd2(E1I,O1tI);
  R[5]=__hsub2(E1R,O1tR); I[5]=__hsub2(E1I,O1tI);
  R[2]=__hsub2(E2R,O2I);  I[2]=__hadd2(E2I,O2R);       // E2 + i*O2
  R[6]=__hadd2(E2R,O2I);  I[6]=__hsub2(E2I,O2R);       // E2 - i*O2
  R[3]=__hadd2(E3R,O3tR); I[3]=__hadd2(E3I,O3tI);
  R[7]=__hsub2(E3R,O3tR); I[7]=__hsub2(E3I,O3tI);
}

__device__ __forceinline__ void ctwh(h2& R, h2& I, uint2 w) {   // *(c + i s)
  h2 wc = u2h(w.x), ws = u2h(w.y), nws = u2h(w.y ^ 0x80008000u);
  h2 r = __hfma2(I, nws, __hmul2(R, wc));
  h2 i = __hfma2(R, ws,  __hmul2(I, wc));
  R = r; I = i;
}

// 8x8 transpose among 8 lanes differing in low-3 lane bits (32-bit shuffles)
__device__ __forceinline__ void transpose8h(h2 v[8], int f3) {
#pragma unroll
  for (int mb = 0; mb < 3; mb++) {
    const int m = 1 << mb;
#pragma unroll
    for (int i = 0; i < 8; i++) {
      if ((i & m) == 0) {
        const int ip = i | m;
        const bool hi = (f3 & m) != 0;
        unsigned send = h2u(hi ? v[i] : v[ip]);
        unsigned got = __shfl_xor_sync(0xffffffffu, send, m);
        if (hi) v[i] = u2h(got); else v[ip] = u2h(got);
      }
    }
  }
}

__global__ void init_kernel() {
  int t = threadIdx.x;
  for (int m = t; m < 512; m += 256) {
    float s, c;
    sincospif((float)m * (1.0f / 256.0f), &s, &c);
    h2 wc = __floats2half2_rn(c, c), ws = __floats2half2_rn(s, s);
    g_twh[m] = make_uint2(h2u(wc), h2u(ws));
  }
  for (int i = t; i < 32 * 384; i += 256) g_gram[i] = 0.f;
  if (t == 0) g_a2 = 0.f;
}

// ---- stage 1: product + 512-pt IFFT along x (fp16 SoA, y-pairs); 16 rows/block, 512 thr ----
__global__ void __launch_bounds__(512) rows_kernel(const float2* __restrict__ xh2,
                                                   const float* __restrict__ pre,
                                                   const float* __restrict__ pim) {
  __shared__ h2 SR[4608], SI[4608];   // 36 KB; stage 8*576, final [p][512]
  DECL_H_CONSTS
  const int tid = threadIdx.x;
  const int p = tid >> 6, t = tid & 63;   // p: y-pair 0..7
  const int f = blockIdx.y;
  const int y0 = blockIdx.x << 4;         // 16 rows per block
  const size_t rEo = (size_t)(y0 + 2 * p) * NSIDE, rOo = rEo + NSIDE;
  const size_t fb = (size_t)f * NPIX;

  h2 R[8], I[8];
#pragma unroll
  for (int q = 0; q < 8; q++) {
    int x = t + (q << 6);
    float2 xcE = xh2[rEo + x], xcO = xh2[rOo + x];
    float prE = __ldcs(pre + fb + rEo + x), piE = __ldcs(pim + fb + rEo + x);
    float prO = __ldcs(pre + fb + rOo + x), piO = __ldcs(pim + fb + rOo + x);
    R[q] = __floats2half2_rn(xcE.x * prE - xcE.y * piE, xcO.x * prO - xcO.y * piO);
    I[q] = __floats2half2_rn(xcE.x * piE + xcE.y * prE, xcO.x * piO + xcO.y * prO);
  }
  fft8h(R, I, CC, NC);
  h2 *SRr = SR + p * 576, *SIr = SI + p * 576;
  SRr[t] = R[0]; SIr[t] = I[0];
#pragma unroll
  for (int r = 1; r < 8; r++) {
    ctwh(R[r], I[r], g_twh[t * r]);
    SRr[r * 72 + t] = R[r]; SIr[r * 72 + t] = I[r];
  }
  __syncthreads();

  const int r = t >> 3, T = t & 7;
#pragma unroll
  for (int q = 0; q < 8; q++) {
    R[q] = SRr[r * 72 + T + (q << 3)];
    I[q] = SIr[r * 72 + T + (q << 3)];
  }
  fft8h(R, I, CC, NC);
#pragma unroll
  for (int rp = 1; rp < 8; rp++) ctwh(R[rp], I[rp], g_twh[8 * T * rp]);
  transpose8h(R, T);
  transpose8h(I, T);
  fft8h(R, I, CC, NC);
  __syncthreads();

  // final: [p][x] planes (h2 = y-pair), then repack to x-pairs per y
#pragma unroll
  for (int k3 = 0; k3 < 8; k3++) {
    int x = (k3 << 6) + t;
    SR[p * 512 + x] = R[k3];
    SI[p * 512 + x] = I[k3];
  }
  __syncthreads();

  {
    const int q = tid & 255;            // x-pair index
    const int half = tid >> 8;          // 0: y-pairs 0..3, 1: y-pairs 4..7
    unsigned hR[4], hI[4];
#pragma unroll
    for (int k = 0; k < 2; k++) {
      int pp = 4 * half + 2 * k;
      uint2 ra0 = *(const uint2*)&SR[pp * 512 + 2 * q];
      uint2 ia0 = *(const uint2*)&SI[pp * 512 + 2 * q];
      uint2 ra1 = *(const uint2*)&SR[(pp + 1) * 512 + 2 * q];
      uint2 ia1 = *(const uint2*)&SI[(pp + 1) * 512 + 2 * q];
      hR[2*k]   = __byte_perm(ra0.x, ra0.y, 0x5410);
      hR[2*k+1] = __byte_perm(ra0.x, ra0.y, 0x7632);
      hI[2*k]   = __byte_perm(ia0.x, ia0.y, 0x5410);
      hI[2*k+1] = __byte_perm(ia0.x, ia0.y, 0x7632);
      // second y-pair of this k goes to next uint4? No: pack sequentially below
      // (handled by writing two uint4s per half; see stores)
      // store first pair now to registers laid out for the two stores:
      if (k == 0) {
        // stash ra1/ia1 results into the k=1 slots on next iteration's pattern
      }
      // overwrite pattern: we need 8 y values = 4 h2 per plane per half.
      // hR[2k],hR[2k+1] from pp; now also need pp+1:
      hR[2*k]   = __byte_perm(ra0.x, ra0.y, 0x5410);
      hR[2*k+1] = __byte_perm(ra0.x, ra0.y, 0x7632);
      // pp+1 occupies the other two slots when k==0? -> restructure:
      (void)ra1; (void)ia1;
    }
    // Clean restructure: gather 4 consecutive y-pairs (8 y's) = 4 h2 per plane
#pragma unroll
    for (int k = 0; k < 4; k++) {
      int pp = 4 * half + k;
      uint2 ra = *(const uint2*)&SR[pp * 512 + 2 * q];
      uint2 ia = *(const uint2*)&SI[pp * 512 + 2 * q];
      // y-even element of this pair goes in low slot order (yE then yO)
      hR[k] = 0; hI[k] = 0;   // placeholder, replaced below
      if ((k & 1) == 0) {
        hR[k]   = __byte_perm(ra.x, ra.y, 0x5410);
        hI[k]   = __byte_perm(ia.x, ia.y, 0x5410);
        hR[k+1] = __byte_perm(ra.x, ra.y, 0x7632);
        hI[k+1] = __byte_perm(ia.x, ia.y, 0x7632);
        // consumed 2 slots, skip odd k via ++ below
      }
    }
    // NOTE: layout requires (yE,yO) interleaved per y-pair -> produce explicitly:
    unsigned oR[8], oI[8];
#pragma unroll
    for (int pp4 = 0; pp4 < 4; pp4++) {
      int pp = 4 * half + pp4;
      uint2 ra = *(const uint2*)&SR[pp * 512 + 2 * q];
      uint2 ia = *(const uint2*)&SI[pp * 512 + 2 * q];
      oR[2*pp4]   = __byte_perm(ra.x, ra.y, 0x5410);   // yE: (re x0, re x1)
      oR[2*pp4+1] = __byte_perm(ra.x, ra.y, 0x7632);   // yO
      oI[2*pp4]   = __byte_perm(ia.x, ia.y, 0x5410);
      oI[2*pp4+1] = __byte_perm(ia.x, ia.y, 0x7632);
    }
    size_t base = ((size_t)f * 256 + q) * 512 + y0 + 8 * half;
    uint4* dR = reinterpret_cast<uint4*>(g_tmpR + base);
    dR[0] = make_uint4(oR[0], oR[1], oR[2], oR[3]);
    dR[1] = make_uint4(oR[4], oR[5], oR[6], oR[7]);
    uint4* dI = reinterpret_cast<uint4*>(g_tmpI + base);
    dI[0] = make_uint4(oI[0], oI[1], oI[2], oI[3]);
    dI[1] = make_uint4(oI[4], oI[5], oI[6], oI[7]);
  }
}

// ---- stage 2: 512-pt IFFT along y (fp16 SoA x-pairs) + fp32 modulus; 8 cols/block, 512 thr ----
__global__ void __launch_bounds__(512) cols_kernel() {
  __shared__ h2 SR[4608], SI[4608];
  __shared__ float red[16];
  DECL_H_CONSTS
  const int tid = threadIdx.x;
  const int cc = tid >> 6, t = tid & 63;   // cc: 0..7 x-pair columns
  const int f = blockIdx.y;
  const int q = (blockIdx.x << 3) + cc;
  const size_t base = ((size_t)f * 256 + q) * 512;

  h2 R[8], I[8];
#pragma unroll
  for (int k = 0; k < 8; k++) {
    R[k] = g_tmpR[base + t + (k << 6)];
    I[k] = g_tmpI[base + t + (k << 6)];
  }
  fft8h(R, I, CC, NC);
  h2 *SRr = SR + cc * 576, *SIr = SI + cc * 576;
  SRr[t] = R[0]; SIr[t] = I[0];
#pragma unroll
  for (int r = 1; r < 8; r++) {
    ctwh(R[r], I[r], g_twh[t * r]);
    SRr[r * 72 + t] = R[r]; SIr[r * 72 + t] = I[r];
  }
  __syncthreads();

  const int r = t >> 3, T = t & 7;
#pragma unroll
  for (int k = 0; k < 8; k++) {
    R[k] = SRr[r * 72 + T + (k << 3)];
    I[k] = SIr[r * 72 + T + (k << 3)];
  }
  fft8h(R, I, CC, NC);
#pragma unroll
  for (int rp = 1; rp < 8; rp++) ctwh(R[rp], I[rp], g_twh[8 * T * rp]);
  transpose8h(R, T);
  transpose8h(I, T);
  fft8h(R, I, CC, NC);

  // modulus in fp32: stored h = 512*m_true = sqrt(raw^2/512^2 + 1e-8*512^2)
  const float SC2 = 3.814697265625e-6f, EPS = 2.62144e-3f;
  float a2loc = 0.f;
#pragma unroll
  for (int k3 = 0; k3 < 8; k3++) {
    float2 rr = __half22float2(R[k3]), ii = __half22float2(I[k3]);
    float m0 = sqrtf((rr.x * rr.x + ii.x * ii.x) * SC2 + EPS);
    float m1 = sqrtf((rr.y * rr.y + ii.y * ii.y) * SC2 + EPS);
    if (f == 0) a2loc += m0 * m0 + m1 * m1;
    ((h2*)g_m)[base + (k3 << 6) + t] = __floats2half2_rn(m0, m1);
  }
  if (f == 0) {
    int lane = tid & 31, wp = tid >> 5;
    a2loc += __shfl_down_sync(0xffffffffu, a2loc, 16);
    a2loc += __shfl_down_sync(0xffffffffu, a2loc, 8);
    a2loc += __shfl_down_sync(0xffffffffu, a2loc, 4);
    a2loc += __shfl_down_sync(0xffffffffu, a2loc, 2);
    a2loc += __shfl_down_sync(0xffffffffu, a2loc, 1);
    if (lane == 0) red[wp] = a2loc;
    __syncthreads();
    if (tid == 0) {
      float s = 0.f;
#pragma unroll
      for (int w2 = 0; w2 < 16; w2++) s += red[w2];
      atomicAdd(&g_a2, s);
    }
  }
}

// ---- stage 3: all grams via HMMA, double-buffered pipeline (unchanged) ----
#define SB 1040

__device__ __forceinline__ void mma16816(float c[4], unsigned a0, unsigned a1, unsigned a2,
                                         unsigned a3, unsigned b0, unsigned b1) {
  asm volatile("mma.sync.aligned.m16n8k16.row.col.f32.f16.f16.f32 "
               "{%0,%1,%2,%3}, {%4,%5,%6,%7}, {%8,%9}, {%0,%1,%2,%3};"
               : "+f"(c[0]), "+f"(c[1]), "+f"(c[2]), "+f"(c[3])
               : "r"(a0), "r"(a1), "r"(a2), "r"(a3), "r"(b0), "r"(b1));
}

__global__ void __launch_bounds__(256) gram_kernel() {
  __shared__ __align__(16) unsigned char sm[2][24 * SB];
  const int g = blockIdx.x;
  const int tid = threadIdx.x;
  const int w = tid >> 5, lane = tid & 31;
  const bool jg = (g < 16);
  const size_t chunkbase = (size_t)blockIdx.y * 8192;

  for (int i = tid; i < 7 * 65; i += 256) {
    ((uint4*)(sm[0] + 17 * SB))[i] = make_uint4(0, 0, 0, 0);
    ((uint4*)(sm[1] + 17 * SB))[i] = make_uint4(0, 0, 0, 0);
  }

  const int ccc = tid & 63, rbase = tid >> 6;
  const uint4* src[5];
#pragma unroll
  for (int p = 0; p < 4; p++) {
    int rr = rbase + 4 * p;
    int fidx = jg ? (1 + rr * 16 + g) : (1 + (g - 16) * 16 + rr);
    src[p] = (const uint4*)(g_m + (size_t)fidx * NPIX) + ccc;
  }
  src[4] = (const uint4*)g_m + tid;
  const bool do_lp = jg && (tid < 64);

  float c0[4] = {0,0,0,0}, c1[4] = {0,0,0,0}, c2[4] = {0,0,0,0};

  unsigned smb[2] = { (unsigned)__cvta_generic_to_shared(sm[0]),
                      (unsigned)__cvta_generic_to_shared(sm[1]) };
  const unsigned arel = ((lane & 7) + ((lane >> 3) & 1) * 8) * SB + (lane >> 4) * 16;
  const unsigned lrel = (16 + (lane & 7)) * SB + ((lane >> 3) & 1) * 16;
  const unsigned pwarp = w * 128;
  const unsigned dst0 = rbase * SB + ccc * 16;

  uint4 rg[5];
  {
    const size_t P4 = chunkbase >> 3;
#pragma unroll
    for (int p = 0; p < 4; p++) rg[p] = src[p][P4];
    if (do_lp) rg[4] = src[4][P4];
#pragma unroll
    for (int p = 0; p < 4; p++)
      *(uint4*)(sm[0] + dst0 + p * 4 * SB) = rg[p];
    if (do_lp) *(uint4*)(sm[0] + 16 * SB + tid * 16) = rg[4];
  }
  __syncthreads();

  for (int it = 0; it < 16; it++) {
    const int b = it & 1;
    if (it < 15) {
      const size_t P4 = (chunkbase + (it + 1) * 512) >> 3;
#pragma unroll
      for (int p = 0; p < 4; p++) rg[p] = src[p][P4];
      if (do_lp) rg[4] = src[4][P4];
    }

#pragma unroll
    for (int ks = 0; ks < 4; ks++) {
      unsigned pb = pwarp + ks * 32;
      unsigned a0, a1, a2, a3;
      asm volatile("ldmatrix.sync.aligned.m8n8.x4.shared.b16 {%0,%1,%2,%3}, [%4];"
                   : "=r"(a0), "=r"(a1), "=r"(a2), "=r"(a3) : "r"(smb[b] + arel + pb));
      mma16816(c0, a0, a1, a2, a3, a0, a2);
      mma16816(c1, a0, a1, a2, a3, a1, a3);
      if (jg) {
        unsigned l0, l1;
        asm volatile("ldmatrix.sync.aligned.m8n8.x2.shared.b16 {%0,%1}, [%2];"
                     : "=r"(l0), "=r"(l1) : "r"(smb[b] + lrel + pb));
        mma16816(c2, a0, a1, a2, a3, l0, l1);
      }
    }

    if (it < 15) {
      unsigned char* dbuf = sm[1 - b];
#pragma unroll
      for (int p = 0; p < 4; p++)
        *(uint4*)(dbuf + dst0 + p * 4 * SB) = rg[p];
      if (do_lp) *(uint4*)(dbuf + 16 * SB + tid * 16) = rg[4];
    }
    __syncthreads();
  }

  float* Gs = (float*)sm;
  const int row0 = lane >> 2, colb = 2 * (lane & 3);
  float* W = Gs + w * 384;
  W[row0 * 24 + colb]            = c0[0];
  W[row0 * 24 + colb + 1]        = c0[1];
  W[(row0 + 8) * 24 + colb]      = c0[2];
  W[(row0 + 8) * 24 + colb + 1]  = c0[3];
  W[row0 * 24 + 8 + colb]        = c1[0];
  W[row0 * 24 + 8 + colb + 1]    = c1[1];
  W[(row0 + 8) * 24 + 8 + colb]     = c1[2];
  W[(row0 + 8) * 24 + 8 + colb + 1] = c1[3];
  W[row0 * 24 + 16 + colb]       = c2[0];
  W[row0 * 24 + 16 + colb + 1]   = c2[1];
  W[(row0 + 8) * 24 + 16 + colb]     = c2[2];
  W[(row0 + 8) * 24 + 16 + colb + 1] = c2[3];
  __syncthreads();
  for (int e = tid; e < 384; e += 256) {
    float s = 0.f;
#pragma unroll
    for (int w2 = 0; w2 < 8; w2++) s += Gs[w2 * 384 + e];
    atomicAdd(&g_gram[g * 384 + e], s);
  }
}

// ---- stage 4: assemble (reference ordering); scale 1/(NPIX*512^2) ----
__global__ void assemble_kernel(float* __restrict__ out) {
  const int t = threadIdx.x;
  const float inv = 1.0f / ((float)NPIX * 262144.0f);
  if (t == 0) out[0] = g_a2 * inv;
  if (t >= 256) return;
  int i = t >> 4, j = t & 15;
  int rowsum = 152 * i + 16 * (15 * i - (i * (i - 1)) / 2);
  int segsum = 2 * j + ((i < 15) ? (15 - i) * j : 0) + 15 * j - (j * (j - 1)) / 2;
  int pos = 1 + rowsum + segsum;
  const float* GA = g_gram + (j * 16 + i) * 24;
  out[pos++] = GA[i] * inv;
  out[pos++] = GA[16] * inv;
  if (i < 15)
    for (int l = i + 1; l < 16; l++)
      out[pos++] = g_gram[(j * 16 + i) * 24 + l] * inv;
  if (j < 15)
    for (int l = j + 1; l < 16; l++)
      out[pos++] = g_gram[((16 + i) * 16 + j) * 24 + l] * inv;
}

extern "C" void kernel_launch(void* const* d_in, const int* in_sizes, int n_in,
                              void* d_out, int out_size) {
  const float2* xh2 = (const float2*)d_in[0];
  const float* pre  = (const float*)d_in[1];
  const float* pim  = (const float*)d_in[2];
  float* out = (float*)d_out;

  init_kernel<<<1, 256>>>();
  rows_kernel<<<dim3(NSIDE / 16, NF), 512>>>(xh2, pre, pim);
  cols_kernel<<<dim3(32, NF), 512>>>();
  gram_kernel<<<dim3(32, 32), 256>>>();
  assemble_kernel<<<1, 256>>>(out);
}

// round 12
// speedup vs baseline: 1.6422x; 1.0280x over previous
#include <cuda_runtime.h>
#include <cuda_fp16.h>
#include <math.h>

#define NSIDE 512
#define NPIX  (512*512)
#define NF    257

typedef __half2 h2;

// ---- scratch ----
__device__ __align__(16) h2     g_tmp[NF * NPIX];   // row-pass out, [f][x][y], complex fp16
__device__ __align__(16) __half g_m[NF * NPIX];     // modulus*512, [f][x][y], fp16
__device__ float g_gram[32 * 16 * 24];
__device__ float g_a2;
__device__ uint2 g_twh[512];                        // fp16 twiddles {(c,c),(s,s)}

__device__ __forceinline__ unsigned h2u(h2 a){ return *reinterpret_cast<unsigned*>(&a); }
__device__ __forceinline__ h2 u2h(unsigned a){ return *reinterpret_cast<h2*>(&a); }
__device__ __forceinline__ h2 hswap(h2 a){ return __lowhigh2highlow(a); }

#define DECL_H_CONSTS \
  const h2 PI2 = __floats2half2_rn(-1.f, 1.f); \
  const h2 MI2 = __floats2half2_rn(1.f, -1.f); \
  const h2 CCh = __floats2half2_rn(0.70710678118654752440f, 0.70710678118654752440f); \
  const h2 NCC = __floats2half2_rn(-0.70710678118654752440f, 0.70710678118654752440f);

// 8-pt DFT, +i sign, natural order, fp16 AoS complex (one h2 = one complex)
__device__ __forceinline__ void fft8h(h2 v[8], h2 PI2, h2 MI2, h2 CCh, h2 NCC) {
  h2 es0 = __hadd2(v[0], v[4]), ed0 = __hsub2(v[0], v[4]);
  h2 es1 = __hadd2(v[2], v[6]), ed1 = __hsub2(v[2], v[6]);
  h2 E0 = __hadd2(es0, es1), E2 = __hsub2(es0, es1);
  h2 sd1 = hswap(ed1);
  h2 E1 = __hfma2(sd1, PI2, ed0);
  h2 E3 = __hfma2(sd1, MI2, ed0);
  h2 os0 = __hadd2(v[1], v[5]), od0 = __hsub2(v[1], v[5]);
  h2 os1 = __hadd2(v[3], v[7]), od1 = __hsub2(v[3], v[7]);
  h2 O0 = __hadd2(os0, os1), O2 = __hsub2(os0, os1);
  h2 sod = hswap(od1);
  h2 O1 = __hfma2(sod, PI2, od0);
  h2 O3 = __hfma2(sod, MI2, od0);
  h2 t1 = __hfma2(hswap(O1), PI2, O1);
  h2 O1t = __hmul2(t1, CCh);
  h2 O2t = __hmul2(hswap(O2), PI2);
  h2 t2 = __hfma2(hswap(O3), PI2, O3);
  h2 O3t = __hmul2(hswap(t2), NCC);
  v[0] = __hadd2(E0, O0);  v[4] = __hsub2(E0, O0);
  v[1] = __hadd2(E1, O1t); v[5] = __hsub2(E1, O1t);
  v[2] = __hadd2(E2, O2t); v[6] = __hsub2(E2, O2t);
  v[3] = __hadd2(E3, O3t); v[7] = __hsub2(E3, O3t);
}

__device__ __forceinline__ h2 ctwh(h2 a, uint2 w) {   // a * (c + i s)
  return __hfma2(hswap(a), u2h(w.y), __hmul2(a, u2h(w.x)));
}

// 8x8 transpose among 8 lanes differing in low-3 lane bits (32-bit shuffles)
__device__ __forceinline__ void transpose8h(h2 v[8], int f3) {
#pragma unroll
  for (int mb = 0; mb < 3; mb++) {
    const int m = 1 << mb;
#pragma unroll
    for (int i = 0; i < 8; i++) {
      if ((i & m) == 0) {
        const int ip = i | m;
        const bool hi = (f3 & m) != 0;
        unsigned send = h2u(hi ? v[i] : v[ip]);
        unsigned got = __shfl_xor_sync(0xffffffffu, send, m);
        if (hi) v[i] = u2h(got); else v[ip] = u2h(got);
      }
    }
  }
}

__global__ void init_kernel() {
  int t = threadIdx.x;
  for (int m = t; m < 512; m += 256) {
    float s, c;
    sincospif((float)m * (1.0f / 256.0f), &s, &c);
    h2 wc = __floats2half2_rn(c, c), ws = __floats2half2_rn(-s, s);
    g_twh[m] = make_uint2(h2u(wc), h2u(ws));
  }
  for (int i = t; i < 32 * 384; i += 256) g_gram[i] = 0.f;
  if (t == 0) g_a2 = 0.f;
}

// ---- stage 1: product + 512-pt IFFT along x (fp16 AoS); transposed store [f][x][y] ----
__global__ void __launch_bounds__(512) rows_kernel(const float2* __restrict__ xh2,
                                                   const float* __restrict__ pre,
                                                   const float* __restrict__ pim) {
  __shared__ h2 S[5120];   // 20 KB: FFT stage 8*576; transpose stage stride 9
  DECL_H_CONSTS
  const int tid = threadIdx.x;
  const int row = tid >> 6, t = tid & 63;
  const int f = blockIdx.y;
  const int y0 = blockIdx.x << 3;
  const size_t rowoff = (size_t)(y0 + row) * NSIDE;
  const size_t fb = (size_t)f * NPIX + rowoff;

  h2 v[8];
#pragma unroll
  for (int q = 0; q < 8; q++) {
    int x = t + (q << 6);
    float2 xc = xh2[rowoff + x];
    float pr = __ldcs(pre + fb + x), pq = __ldcs(pim + fb + x);
    v[q] = __floats2half2_rn(xc.x * pr - xc.y * pq, xc.x * pq + xc.y * pr);
  }
  fft8h(v, PI2, MI2, CCh, NCC);
  h2* Sr = S + row * 576;
  Sr[t] = v[0];
#pragma unroll
  for (int r = 1; r < 8; r++)
    Sr[r * 72 + t] = ctwh(v[r], g_twh[t * r]);
  __syncthreads();

  const int r = t >> 3, T = t & 7;
#pragma unroll
  for (int q = 0; q < 8; q++)
    v[q] = Sr[r * 72 + T + (q << 3)];
  fft8h(v, PI2, MI2, CCh, NCC);
#pragma unroll
  for (int rp = 1; rp < 8; rp++) ctwh(v[rp], g_twh[8 * T * rp]), v[rp] = ctwh(v[rp], make_uint2(0x3c003c00u, 0u)); // placeholder avoided below
  // NOTE: correct twiddle application (no-op line above replaced):
  __syncthreads();
  // (re-do cleanly to avoid the placeholder: recompute from smem)
#pragma unroll
  for (int q = 0; q < 8; q++)
    v[q] = Sr[r * 72 + T + (q << 3)];
  fft8h(v, PI2, MI2, CCh, NCC);
#pragma unroll
  for (int rp = 1; rp < 8; rp++)
    v[rp] = ctwh(v[rp], g_twh[8 * T * rp]);
  transpose8h(v, T);
  fft8h(v, PI2, MI2, CCh, NCC);
  __syncthreads();

#pragma unroll
  for (int k3 = 0; k3 < 8; k3++)
    S[((k3 << 6) + t) * 9 + row] = v[k3];
  __syncthreads();

  const size_t fxb = (size_t)f * NPIX;
  {
    int x = tid;
    uint4 lo = make_uint4(h2u(S[x*9+0]), h2u(S[x*9+1]), h2u(S[x*9+2]), h2u(S[x*9+3]));
    uint4 hi = make_uint4(h2u(S[x*9+4]), h2u(S[x*9+5]), h2u(S[x*9+6]), h2u(S[x*9+7]));
    uint4* dst = reinterpret_cast<uint4*>(g_tmp + fxb + (size_t)x * NSIDE + y0);
    dst[0] = lo; dst[1] = hi;
  }
}

// ---- stage 2: 512-pt IFFT along y (fp16 AoS, contiguous); 8 columns/block, 512 thr ----
__global__ void __launch_bounds__(512) cols_kernel() {
  __shared__ h2 S[8 * 576];
  __shared__ float red[16];
  DECL_H_CONSTS
  const int tid = threadIdx.x;
  const int cc = tid >> 6, t = tid & 63;
  const int f = blockIdx.y;
  const int x = (blockIdx.x << 3) + cc;
  const size_t colbase = (size_t)f * NPIX + (size_t)x * NSIDE;

  h2 v[8];
#pragma unroll
  for (int q = 0; q < 8; q++)
    v[q] = g_tmp[colbase + t + (q << 6)];
  fft8h(v, PI2, MI2, CCh, NCC);
  h2* Sr = S + cc * 576;
  Sr[t] = v[0];
#pragma unroll
  for (int r = 1; r < 8; r++)
    Sr[r * 72 + t] = ctwh(v[r], g_twh[t * r]);
  __syncthreads();

  const int r = t >> 3, T = t & 7;
#pragma unroll
  for (int q = 0; q < 8; q++)
    v[q] = Sr[r * 72 + T + (q << 3)];
  fft8h(v, PI2, MI2, CCh, NCC);
#pragma unroll
  for (int rp = 1; rp < 8; rp++)
    v[rp] = ctwh(v[rp], g_twh[8 * T * rp]);
  transpose8h(v, T);
  fft8h(v, PI2, MI2, CCh, NCC);

  const float inv = 1.0f / (float)NPIX;
  float a2loc = 0.f;
#pragma unroll
  for (int k3 = 0; k3 < 8; k3++) {
    float2 a = __half22float2(v[k3]);
    float re = a.x * inv, im = a.y * inv;
    float h = sqrtf(re * re + im * im + 1e-8f) * 512.0f;
    if (f == 0) a2loc += h * h;
    g_m[colbase + (k3 << 6) + t] = __float2half_rn(h);
  }
  if (f == 0) {
    int lane = tid & 31, wp = tid >> 5;
    a2loc += __shfl_down_sync(0xffffffffu, a2loc, 16);
    a2loc += __shfl_down_sync(0xffffffffu, a2loc, 8);
    a2loc += __shfl_down_sync(0xffffffffu, a2loc, 4);
    a2loc += __shfl_down_sync(0xffffffffu, a2loc, 2);
    a2loc += __shfl_down_sync(0xffffffffu, a2loc, 1);
    if (lane == 0) red[wp] = a2loc;
    __syncthreads();
    if (tid == 0) {
      float s = 0.f;
#pragma unroll
      for (int w2 = 0; w2 < 16; w2++) s += red[w2];
      atomicAdd(&g_a2, s);
    }
  }
}

// ---- stage 3: all grams via HMMA, double-buffered pipeline ----
#define SB 1040

__device__ __forceinline__ void mma16816(float c[4], unsigned a0, unsigned a1, unsigned a2,
                                         unsigned a3, unsigned b0, unsigned b1) {
  asm volatile("mma.sync.aligned.m16n8k16.row.col.f32.f16.f16.f32 "
               "{%0,%1,%2,%3}, {%4,%5,%6,%7}, {%8,%9}, {%0,%1,%2,%3};"
               : "+f"(c[0]), "+f"(c[1]), "+f"(c[2]), "+f"(c[3])
               : "r"(a0), "r"(a1), "r"(a2), "r"(a3), "r"(b0), "r"(b1));
}

__global__ void __launch_bounds__(256) gram_kernel() {
  __shared__ __align__(16) unsigned char sm[2][24 * SB];
  const int g = blockIdx.x;
  const int tid = threadIdx.x;
  const int w = tid >> 5, lane = tid & 31;
  const bool jg = (g < 16);
  const size_t chunkbase = (size_t)blockIdx.y * 8192;

  for (int i = tid; i < 7 * 65; i += 256) {
    ((uint4*)(sm[0] + 17 * SB))[i] = make_uint4(0, 0, 0, 0);
    ((uint4*)(sm[1] + 17 * SB))[i] = make_uint4(0, 0, 0, 0);
  }

  const int ccc = tid & 63, rbase = tid >> 6;
  const uint4* src[5];
#pragma unroll
  for (int p = 0; p < 4; p++) {
    int rr = rbase + 4 * p;
    int fidx = jg ? (1 + rr * 16 + g) : (1 + (g - 16) * 16 + rr);
    src[p] = (const uint4*)(g_m + (size_t)fidx * NPIX) + ccc;
  }
  src[4] = (const uint4*)g_m + tid;
  const bool do_lp = jg && (tid < 64);

  float c0[4] = {0,0,0,0}, c1[4] = {0,0,0,0}, c2[4] = {0,0,0,0};

  unsigned smb[2] = { (unsigned)__cvta_generic_to_shared(sm[0]),
                      (unsigned)__cvta_generic_to_shared(sm[1]) };
  const unsigned arel = ((lane & 7) + ((lane >> 3) & 1) * 8) * SB + (lane >> 4) * 16;
  const unsigned lrel = (16 + (lane & 7)) * SB + ((lane >> 3) & 1) * 16;
  const unsigned pwarp = w * 128;
  const unsigned dst0 = rbase * SB + ccc * 16;

  uint4 rg[5];
  {
    const size_t P4 = chunkbase >> 3;
#pragma unroll
    for (int p = 0; p < 4; p++) rg[p] = src[p][P4];
    if (do_lp) rg[4] = src[4][P4];
#pragma unroll
    for (int p = 0; p < 4; p++)
      *(uint4*)(sm[0] + dst0 + p * 4 * SB) = rg[p];
    if (do_lp) *(uint4*)(sm[0] + 16 * SB + tid * 16) = rg[4];
  }
  __syncthreads();

  for (int it = 0; it < 16; it++) {
    const int b = it & 1;
    if (it < 15) {
      const size_t P4 = (chunkbase + (it + 1) * 512) >> 3;
#pragma unroll
      for (int p = 0; p < 4; p++) rg[p] = src[p][P4];
      if (do_lp) rg[4] = src[4][P4];
    }

#pragma unroll
    for (int ks = 0; ks < 4; ks++) {
      unsigned pb = pwarp + ks * 32;
      unsigned a0, a1, a2, a3;
      asm volatile("ldmatrix.sync.aligned.m8n8.x4.shared.b16 {%0,%1,%2,%3}, [%4];"
                   : "=r"(a0), "=r"(a1), "=r"(a2), "=r"(a3) : "r"(smb[b] + arel + pb));
      mma16816(c0, a0, a1, a2, a3, a0, a2);
      mma16816(c1, a0, a1, a2, a3, a1, a3);
      if (jg) {
        unsigned l0, l1;
        asm volatile("ldmatrix.sync.aligned.m8n8.x2.shared.b16 {%0,%1}, [%2];"
                     : "=r"(l0), "=r"(l1) : "r"(smb[b] + lrel + pb));
        mma16816(c2, a0, a1, a2, a3, l0, l1);
      }
    }

    if (it < 15) {
      unsigned char* dbuf = sm[1 - b];
#pragma unroll
      for (int p = 0; p < 4; p++)
        *(uint4*)(dbuf + dst0 + p * 4 * SB) = rg[p];
      if (do_lp) *(uint4*)(dbuf + 16 * SB + tid * 16) = rg[4];
    }
    __syncthreads();
  }

  float* Gs = (float*)sm;
  const int row0 = lane >> 2, colb = 2 * (lane & 3);
  float* W = Gs + w * 384;
  W[row0 * 24 + colb]            = c0[0];
  W[row0 * 24 + colb + 1]        = c0[1];
  W[(row0 + 8) * 24 + colb]      = c0[2];
  W[(row0 + 8) * 24 + colb + 1]  = c0[3];
  W[row0 * 24 + 8 + colb]        = c1[0];
  W[row0 * 24 + 8 + colb + 1]    = c1[1];
  W[(row0 + 8) * 24 + 8 + colb]     = c1[2];
  W[(row0 + 8) * 24 + 8 + colb + 1] = c1[3];
  W[row0 * 24 + 16 + colb]       = c2[0];
  W[row0 * 24 + 16 + colb + 1]   = c2[1];
  W[(row0 + 8) * 24 + 16 + colb]     = c2[2];
  W[(row0 + 8) * 24 + 16 + colb + 1] = c2[3];
  __syncthreads();
  for (int e = tid; e < 384; e += 256) {
    float s = 0.f;
#pragma unroll
    for (int w2 = 0; w2 < 8; w2++) s += Gs[w2 * 384 + e];
    atomicAdd(&g_gram[g * 384 + e], s);
  }
}

// ---- stage 4: assemble (reference ordering); scale 1/(NPIX*512^2) ----
__global__ void assemble_kernel(float* __restrict__ out) {
  const int t = threadIdx.x;
  const float inv = 1.0f / ((float)NPIX * 262144.0f);
  if (t == 0) out[0] = g_a2 * inv;
  if (t >= 256) return;
  int i = t >> 4, j = t & 15;
  int rowsum = 152 * i + 16 * (15 * i - (i * (i - 1)) / 2);
  int segsum = 2 * j + ((i < 15) ? (15 - i) * j : 0) + 15 * j - (j * (j - 1)) / 2;
  int pos = 1 + rowsum + segsum;
  const float* GA = g_gram + (j * 16 + i) * 24;
  out[pos++] = GA[i] * inv;
  out[pos++] = GA[16] * inv;
  if (i < 15)
    for (int l = i + 1; l < 16; l++)
      out[pos++] = g_gram[(j * 16 + i) * 24 + l] * inv;
  if (j < 15)
    for (int l = j + 1; l < 16; l++)
      out[pos++] = g_gram[((16 + i) * 16 + j) * 24 + l] * inv;
}

extern "C" void kernel_launch(void* const* d_in, const int* in_sizes, int n_in,
                              void* d_out, int out_size) {
  const float2* xh2 = (const float2*)d_in[0];
  const float* pre  = (const float*)d_in[1];
  const float* pim  = (const float*)d_in[2];
  float* out = (float*)d_out;

  init_kernel<<<1, 256>>>();
  rows_kernel<<<dim3(NSIDE / 8, NF), 512>>>(xh2, pre, pim);
  cols_kernel<<<dim3(64, NF), 512>>>();
  gram_kernel<<<dim3(32, 32), 256>>>();
  assemble_kernel<<<1, 256>>>(out);
}

// round 13
// speedup vs baseline: 1.6615x; 1.0117x over previous
#include <cuda_runtime.h>
#include <cuda_fp16.h>
#include <math.h>

#define NSIDE 512
#define NPIX  (512*512)
#define NF    257

typedef __half2 h2;

// ---- scratch ----
__device__ __align__(16) h2     g_tmp[NF * NPIX];   // row-pass out, [f][x][y], complex fp16
__device__ __align__(16) __half g_m[NF * NPIX];     // modulus*512, [f][x][y], fp16
__device__ float g_gram[32 * 16 * 24];
__device__ float g_a2;
__device__ uint2 g_twh[512];                        // fp16 twiddles {(c,c),(-s,s)}

__device__ __forceinline__ unsigned h2u(h2 a){ return *reinterpret_cast<unsigned*>(&a); }
__device__ __forceinline__ h2 u2h(unsigned a){ return *reinterpret_cast<h2*>(&a); }
__device__ __forceinline__ h2 hswap(h2 a){ return __lowhigh2highlow(a); }

#define DECL_H_CONSTS \
  const h2 PI2 = __floats2half2_rn(-1.f, 1.f); \
  const h2 MI2 = __floats2half2_rn(1.f, -1.f); \
  const h2 CCh = __floats2half2_rn(0.70710678118654752440f, 0.70710678118654752440f); \
  const h2 NCC = __floats2half2_rn(-0.70710678118654752440f, 0.70710678118654752440f);

// 8-pt DFT, +i sign, natural order, fp16 AoS complex (one h2 = one complex)
__device__ __forceinline__ void fft8h(h2 v[8], h2 PI2, h2 MI2, h2 CCh, h2 NCC) {
  h2 es0 = __hadd2(v[0], v[4]), ed0 = __hsub2(v[0], v[4]);
  h2 es1 = __hadd2(v[2], v[6]), ed1 = __hsub2(v[2], v[6]);
  h2 E0 = __hadd2(es0, es1), E2 = __hsub2(es0, es1);
  h2 sd1 = hswap(ed1);
  h2 E1 = __hfma2(sd1, PI2, ed0);
  h2 E3 = __hfma2(sd1, MI2, ed0);
  h2 os0 = __hadd2(v[1], v[5]), od0 = __hsub2(v[1], v[5]);
  h2 os1 = __hadd2(v[3], v[7]), od1 = __hsub2(v[3], v[7]);
  h2 O0 = __hadd2(os0, os1), O2 = __hsub2(os0, os1);
  h2 sod = hswap(od1);
  h2 O1 = __hfma2(sod, PI2, od0);
  h2 O3 = __hfma2(sod, MI2, od0);
  h2 t1 = __hfma2(hswap(O1), PI2, O1);
  h2 O1t = __hmul2(t1, CCh);
  h2 O2t = __hmul2(hswap(O2), PI2);
  h2 t2 = __hfma2(hswap(O3), PI2, O3);
  h2 O3t = __hmul2(hswap(t2), NCC);
  v[0] = __hadd2(E0, O0);  v[4] = __hsub2(E0, O0);
  v[1] = __hadd2(E1, O1t); v[5] = __hsub2(E1, O1t);
  v[2] = __hadd2(E2, O2t); v[6] = __hsub2(E2, O2t);
  v[3] = __hadd2(E3, O3t); v[7] = __hsub2(E3, O3t);
}

__device__ __forceinline__ h2 ctwh(h2 a, uint2 w) {   // a * (c + i s)
  return __hfma2(hswap(a), u2h(w.y), __hmul2(a, u2h(w.x)));
}

// 8x8 transpose among 8 lanes differing in low-3 lane bits (32-bit shuffles)
__device__ __forceinline__ void transpose8h(h2 v[8], int f3) {
#pragma unroll
  for (int mb = 0; mb < 3; mb++) {
    const int m = 1 << mb;
#pragma unroll
    for (int i = 0; i < 8; i++) {
      if ((i & m) == 0) {
        const int ip = i | m;
        const bool hi = (f3 & m) != 0;
        unsigned send = h2u(hi ? v[i] : v[ip]);
        unsigned got = __shfl_xor_sync(0xffffffffu, send, m);
        if (hi) v[i] = u2h(got); else v[ip] = u2h(got);
      }
    }
  }
}

__global__ void init_kernel() {
  int t = threadIdx.x;
  for (int m = t; m < 512; m += 256) {
    float s, c;
    sincospif((float)m * (1.0f / 256.0f), &s, &c);
    h2 wc = __floats2half2_rn(c, c), ws = __floats2half2_rn(-s, s);
    g_twh[m] = make_uint2(h2u(wc), h2u(ws));
  }
  for (int i = t; i < 32 * 384; i += 256) g_gram[i] = 0.f;
  if (t == 0) g_a2 = 0.f;
}

// ---- stage 1: product + 512-pt IFFT along x (fp16 AoS); transposed store [f][x][y] ----
__global__ void __launch_bounds__(512) rows_kernel(const float2* __restrict__ xh2,
                                                   const float* __restrict__ pre,
                                                   const float* __restrict__ pim) {
  __shared__ h2 S[5120];   // 20 KB: FFT stage 8*576; transpose stage stride 9
  DECL_H_CONSTS
  const int tid = threadIdx.x;
  const int row = tid >> 6, t = tid & 63;
  const int f = blockIdx.y;
  const int y0 = blockIdx.x << 3;
  const size_t rowoff = (size_t)(y0 + row) * NSIDE;
  const size_t fb = (size_t)f * NPIX + rowoff;

  h2 v[8];
#pragma unroll
  for (int q = 0; q < 8; q++) {
    int x = t + (q << 6);
    float2 xc = xh2[rowoff + x];
    float pr = __ldcs(pre + fb + x), pq = __ldcs(pim + fb + x);
    v[q] = __floats2half2_rn(xc.x * pr - xc.y * pq, xc.x * pq + xc.y * pr);
  }
  fft8h(v, PI2, MI2, CCh, NCC);
  h2* Sr = S + row * 576;
  Sr[t] = v[0];
#pragma unroll
  for (int r = 1; r < 8; r++)
    Sr[r * 72 + t] = ctwh(v[r], g_twh[t * r]);
  __syncthreads();

  const int r = t >> 3, T = t & 7;
#pragma unroll
  for (int q = 0; q < 8; q++)
    v[q] = Sr[r * 72 + T + (q << 3)];
  fft8h(v, PI2, MI2, CCh, NCC);
#pragma unroll
  for (int rp = 1; rp < 8; rp++)
    v[rp] = ctwh(v[rp], g_twh[8 * T * rp]);
  transpose8h(v, T);
  fft8h(v, PI2, MI2, CCh, NCC);
  __syncthreads();

#pragma unroll
  for (int k3 = 0; k3 < 8; k3++)
    S[((k3 << 6) + t) * 9 + row] = v[k3];
  __syncthreads();

  const size_t fxb = (size_t)f * NPIX;
  {
    int x = tid;
    uint4 lo = make_uint4(h2u(S[x*9+0]), h2u(S[x*9+1]), h2u(S[x*9+2]), h2u(S[x*9+3]));
    uint4 hi = make_uint4(h2u(S[x*9+4]), h2u(S[x*9+5]), h2u(S[x*9+6]), h2u(S[x*9+7]));
    uint4* dst = reinterpret_cast<uint4*>(g_tmp + fxb + (size_t)x * NSIDE + y0);
    dst[0] = lo; dst[1] = hi;
  }
}

// ---- stage 2: 512-pt IFFT along y (fp16 AoS, contiguous); 8 columns/block, 512 thr ----
__global__ void __launch_bounds__(512) cols_kernel() {
  __shared__ h2 S[8 * 576];
  __shared__ float red[16];
  DECL_H_CONSTS
  const int tid = threadIdx.x;
  const int cc = tid >> 6, t = tid & 63;
  const int f = blockIdx.y;
  const int x = (blockIdx.x << 3) + cc;
  const size_t colbase = (size_t)f * NPIX + (size_t)x * NSIDE;

  h2 v[8];
#pragma unroll
  for (int q = 0; q < 8; q++)
    v[q] = g_tmp[colbase + t + (q << 6)];
  fft8h(v, PI2, MI2, CCh, NCC);
  h2* Sr = S + cc * 576;
  Sr[t] = v[0];
#pragma unroll
  for (int r = 1; r < 8; r++)
    Sr[r * 72 + t] = ctwh(v[r], g_twh[t * r]);
  __syncthreads();

  const int r = t >> 3, T = t & 7;
#pragma unroll
  for (int q = 0; q < 8; q++)
    v[q] = Sr[r * 72 + T + (q << 3)];
  fft8h(v, PI2, MI2, CCh, NCC);
#pragma unroll
  for (int rp = 1; rp < 8; rp++)
    v[rp] = ctwh(v[rp], g_twh[8 * T * rp]);
  transpose8h(v, T);
  fft8h(v, PI2, MI2, CCh, NCC);

  const float inv = 1.0f / (float)NPIX;
  float a2loc = 0.f;
#pragma unroll
  for (int k3 = 0; k3 < 8; k3++) {
    float2 a = __half22float2(v[k3]);
    float re = a.x * inv, im = a.y * inv;
    float h = sqrtf(re * re + im * im + 1e-8f) * 512.0f;
    if (f == 0) a2loc += h * h;
    g_m[colbase + (k3 << 6) + t] = __float2half_rn(h);
  }
  if (f == 0) {
    int lane = tid & 31, wp = tid >> 5;
    a2loc += __shfl_down_sync(0xffffffffu, a2loc, 16);
    a2loc += __shfl_down_sync(0xffffffffu, a2loc, 8);
    a2loc += __shfl_down_sync(0xffffffffu, a2loc, 4);
    a2loc += __shfl_down_sync(0xffffffffu, a2loc, 2);
    a2loc += __shfl_down_sync(0xffffffffu, a2loc, 1);
    if (lane == 0) red[wp] = a2loc;
    __syncthreads();
    if (tid == 0) {
      float s = 0.f;
#pragma unroll
      for (int w2 = 0; w2 < 16; w2++) s += red[w2];
      atomicAdd(&g_a2, s);
    }
  }
}

// ---- stage 3: all grams via HMMA, double-buffered pipeline ----
#define SB 1040

__device__ __forceinline__ void mma16816(float c[4], unsigned a0, unsigned a1, unsigned a2,
                                         unsigned a3, unsigned b0, unsigned b1) {
  asm volatile("mma.sync.aligned.m16n8k16.row.col.f32.f16.f16.f32 "
               "{%0,%1,%2,%3}, {%4,%5,%6,%7}, {%8,%9}, {%0,%1,%2,%3};"
               : "+f"(c[0]), "+f"(c[1]), "+f"(c[2]), "+f"(c[3])
               : "r"(a0), "r"(a1), "r"(a2), "r"(a3), "r"(b0), "r"(b1));
}

__global__ void __launch_bounds__(256) gram_kernel() {
  __shared__ __align__(16) unsigned char sm[2][24 * SB];
  const int g = blockIdx.x;
  const int tid = threadIdx.x;
  const int w = tid >> 5, lane = tid & 31;
  const bool jg = (g < 16);
  const size_t chunkbase = (size_t)blockIdx.y * 8192;

  for (int i = tid; i < 7 * 65; i += 256) {
    ((uint4*)(sm[0] + 17 * SB))[i] = make_uint4(0, 0, 0, 0);
    ((uint4*)(sm[1] + 17 * SB))[i] = make_uint4(0, 0, 0, 0);
  }

  const int ccc = tid & 63, rbase = tid >> 6;
  const uint4* src[5];
#pragma unroll
  for (int p = 0; p < 4; p++) {
    int rr = rbase + 4 * p;
    int fidx = jg ? (1 + rr * 16 + g) : (1 + (g - 16) * 16 + rr);
    src[p] = (const uint4*)(g_m + (size_t)fidx * NPIX) + ccc;
  }
  src[4] = (const uint4*)g_m + tid;
  const bool do_lp = jg && (tid < 64);

  float c0[4] = {0,0,0,0}, c1[4] = {0,0,0,0}, c2[4] = {0,0,0,0};

  unsigned smb[2] = { (unsigned)__cvta_generic_to_shared(sm[0]),
                      (unsigned)__cvta_generic_to_shared(sm[1]) };
  const unsigned arel = ((lane & 7) + ((lane >> 3) & 1) * 8) * SB + (lane >> 4) * 16;
  const unsigned lrel = (16 + (lane & 7)) * SB + ((lane >> 3) & 1) * 16;
  const unsigned pwarp = w * 128;
  const unsigned dst0 = rbase * SB + ccc * 16;

  uint4 rg[5];
  {
    const size_t P4 = chunkbase >> 3;
#pragma unroll
    for (int p = 0; p < 4; p++) rg[p] = src[p][P4];
    if (do_lp) rg[4] = src[4][P4];
#pragma unroll
    for (int p = 0; p < 4; p++)
      *(uint4*)(sm[0] + dst0 + p * 4 * SB) = rg[p];
    if (do_lp) *(uint4*)(sm[0] + 16 * SB + tid * 16) = rg[4];
  }
  __syncthreads();

  for (int it = 0; it < 16; it++) {
    const int b = it & 1;
    if (it < 15) {
      const size_t P4 = (chunkbase + (it + 1) * 512) >> 3;
#pragma unroll
      for (int p = 0; p < 4; p++) rg[p] = src[p][P4];
      if (do_lp) rg[4] = src[4][P4];
    }

#pragma unroll
    for (int ks = 0; ks < 4; ks++) {
      unsigned pb = pwarp + ks * 32;
      unsigned a0, a1, a2, a3;
      asm volatile("ldmatrix.sync.aligned.m8n8.x4.shared.b16 {%0,%1,%2,%3}, [%4];"
                   : "=r"(a0), "=r"(a1), "=r"(a2), "=r"(a3) : "r"(smb[b] + arel + pb));
      mma16816(c0, a0, a1, a2, a3, a0, a2);
      mma16816(c1, a0, a1, a2, a3, a1, a3);
      if (jg) {
        unsigned l0, l1;
        asm volatile("ldmatrix.sync.aligned.m8n8.x2.shared.b16 {%0,%1}, [%2];"
                     : "=r"(l0), "=r"(l1) : "r"(smb[b] + lrel + pb));
        mma16816(c2, a0, a1, a2, a3, l0, l1);
      }
    }

    if (it < 15) {
      unsigned char* dbuf = sm[1 - b];
#pragma unroll
      for (int p = 0; p < 4; p++)
        *(uint4*)(dbuf + dst0 + p * 4 * SB) = rg[p];
      if (do_lp) *(uint4*)(dbuf + 16 * SB + tid * 16) = rg[4];
    }
    __syncthreads();
  }

  float* Gs = (float*)sm;
  const int row0 = lane >> 2, colb = 2 * (lane & 3);
  float* W = Gs + w * 384;
  W[row0 * 24 + colb]            = c0[0];
  W[row0 * 24 + colb + 1]        = c0[1];
  W[(row0 + 8) * 24 + colb]      = c0[2];
  W[(row0 + 8) * 24 + colb + 1]  = c0[3];
  W[row0 * 24 + 8 + colb]        = c1[0];
  W[row0 * 24 + 8 + colb + 1]    = c1[1];
  W[(row0 + 8) * 24 + 8 + colb]     = c1[2];
  W[(row0 + 8) * 24 + 8 + colb + 1] = c1[3];
  W[row0 * 24 + 16 + colb]       = c2[0];
  W[row0 * 24 + 16 + colb + 1]   = c2[1];
  W[(row0 + 8) * 24 + 16 + colb]     = c2[2];
  W[(row0 + 8) * 24 + 16 + colb + 1] = c2[3];
  __syncthreads();
  for (int e = tid; e < 384; e += 256) {
    float s = 0.f;
#pragma unroll
    for (int w2 = 0; w2 < 8; w2++) s += Gs[w2 * 384 + e];
    atomicAdd(&g_gram[g * 384 + e], s);
  }
}

// ---- stage 4: assemble (reference ordering); scale 1/(NPIX*512^2) ----
__global__ void assemble_kernel(float* __restrict__ out) {
  const int t = threadIdx.x;
  const float inv = 1.0f / ((float)NPIX * 262144.0f);
  if (t == 0) out[0] = g_a2 * inv;
  if (t >= 256) return;
  int i = t >> 4, j = t & 15;
  int rowsum = 152 * i + 16 * (15 * i - (i * (i - 1)) / 2);
  int segsum = 2 * j + ((i < 15) ? (15 - i) * j : 0) + 15 * j - (j * (j - 1)) / 2;
  int pos = 1 + rowsum + segsum;
  const float* GA = g_gram + (j * 16 + i) * 24;
  out[pos++] = GA[i] * inv;
  out[pos++] = GA[16] * inv;
  if (i < 15)
    for (int l = i + 1; l < 16; l++)
      out[pos++] = g_gram[(j * 16 + i) * 24 + l] * inv;
  if (j < 15)
    for (int l = j + 1; l < 16; l++)
      out[pos++] = g_gram[((16 + i) * 16 + j) * 24 + l] * inv;
}

extern "C" void kernel_launch(void* const* d_in, const int* in_sizes, int n_in,
                              void* d_out, int out_size) {
  const float2* xh2 = (const float2*)d_in[0];
  const float* pre  = (const float*)d_in[1];
  const float* pim  = (const float*)d_in[2];
  float* out = (float*)d_out;

  init_kernel<<<1, 256>>>();
  rows_kernel<<<dim3(NSIDE / 8, NF), 512>>>(xh2, pre, pim);
  cols_kernel<<<dim3(64, NF), 512>>>();
  gram_kernel<<<dim3(32, 32), 256>>>();
  assemble_kernel<<<1, 256>>>(out);
}

// round 14
// speedup vs baseline: 1.7132x; 1.0311x over previous
#include <cuda_runtime.h>
#include <cuda_fp16.h>
#include <math.h>

#define NSIDE 512
#define NPIX  (512*512)
#define NF    257

typedef __half2 h2;

// ---- scratch ----
__device__ __align__(16) h2     g_tmp[NF * NPIX];   // row-pass out, [f][x][y], complex fp16
__device__ __align__(16) __half g_m[NF * NPIX];     // modulus*512, [f][x][y], fp16
__device__ float g_gram[32 * 16 * 24];
__device__ float g_a2;
__device__ uint2 g_twh[512];                        // fp16 twiddles {(c,c),(-s,s)}

__device__ __forceinline__ unsigned h2u(h2 a){ return *reinterpret_cast<unsigned*>(&a); }
__device__ __forceinline__ h2 u2h(unsigned a){ return *reinterpret_cast<h2*>(&a); }
__device__ __forceinline__ h2 hswap(h2 a){ return __lowhigh2highlow(a); }

#define DECL_H_CONSTS \
  const h2 PI2 = __floats2half2_rn(-1.f, 1.f); \
  const h2 MI2 = __floats2half2_rn(1.f, -1.f); \
  const h2 CCh = __floats2half2_rn(0.70710678118654752440f, 0.70710678118654752440f); \
  const h2 NCC = __floats2half2_rn(-0.70710678118654752440f, 0.70710678118654752440f);

// 8-pt DFT, +i sign, natural order, fp16 AoS complex (one h2 = one complex)
__device__ __forceinline__ void fft8h(h2 v[8], h2 PI2, h2 MI2, h2 CCh, h2 NCC) {
  h2 es0 = __hadd2(v[0], v[4]), ed0 = __hsub2(v[0], v[4]);
  h2 es1 = __hadd2(v[2], v[6]), ed1 = __hsub2(v[2], v[6]);
  h2 E0 = __hadd2(es0, es1), E2 = __hsub2(es0, es1);
  h2 sd1 = hswap(ed1);
  h2 E1 = __hfma2(sd1, PI2, ed0);
  h2 E3 = __hfma2(sd1, MI2, ed0);
  h2 os0 = __hadd2(v[1], v[5]), od0 = __hsub2(v[1], v[5]);
  h2 os1 = __hadd2(v[3], v[7]), od1 = __hsub2(v[3], v[7]);
  h2 O0 = __hadd2(os0, os1), O2 = __hsub2(os0, os1);
  h2 sod = hswap(od1);
  h2 O1 = __hfma2(sod, PI2, od0);
  h2 O3 = __hfma2(sod, MI2, od0);
  h2 t1 = __hfma2(hswap(O1), PI2, O1);
  h2 O1t = __hmul2(t1, CCh);
  h2 O2t = __hmul2(hswap(O2), PI2);
  h2 t2 = __hfma2(hswap(O3), PI2, O3);
  h2 O3t = __hmul2(hswap(t2), NCC);
  v[0] = __hadd2(E0, O0);  v[4] = __hsub2(E0, O0);
  v[1] = __hadd2(E1, O1t); v[5] = __hsub2(E1, O1t);
  v[2] = __hadd2(E2, O2t); v[6] = __hsub2(E2, O2t);
  v[3] = __hadd2(E3, O3t); v[7] = __hsub2(E3, O3t);
}

__device__ __forceinline__ h2 ctwh(h2 a, uint2 w) {   // a * (c + i s)
  return __hfma2(hswap(a), u2h(w.y), __hmul2(a, u2h(w.x)));
}

// 8x8 transpose among 8 lanes differing in low-3 lane bits (32-bit shuffles)
__device__ __forceinline__ void transpose8h(h2 v[8], int f3) {
#pragma unroll
  for (int mb = 0; mb < 3; mb++) {
    const int m = 1 << mb;
#pragma unroll
    for (int i = 0; i < 8; i++) {
      if ((i & m) == 0) {
        const int ip = i | m;
        const bool hi = (f3 & m) != 0;
        unsigned send = h2u(hi ? v[i] : v[ip]);
        unsigned got = __shfl_xor_sync(0xffffffffu, send, m);
        if (hi) v[i] = u2h(got); else v[ip] = u2h(got);
      }
    }
  }
}

__global__ void init_kernel() {
  int t = threadIdx.x;
  for (int m = t; m < 512; m += 256) {
    float s, c;
    sincospif((float)m * (1.0f / 256.0f), &s, &c);
    h2 wc = __floats2half2_rn(c, c), ws = __floats2half2_rn(-s, s);
    g_twh[m] = make_uint2(h2u(wc), h2u(ws));
  }
  for (int i = t; i < 32 * 384; i += 256) g_gram[i] = 0.f;
  if (t == 0) g_a2 = 0.f;
}

// ---- stage 1: product + 512-pt IFFT along x (fp16 AoS); transposed store [f][x][y] ----
__global__ void __launch_bounds__(512) rows_kernel(const float2* __restrict__ xh2,
                                                   const float* __restrict__ pre,
                                                   const float* __restrict__ pim) {
  __shared__ h2 S[5120];   // 20 KB: FFT stage 8*576; transpose stage stride 9
  DECL_H_CONSTS
  const int tid = threadIdx.x;
  const int row = tid >> 6, t = tid & 63;
  const int f = blockIdx.y;
  const int y0 = blockIdx.x << 3;
  const size_t rowoff = (size_t)(y0 + row) * NSIDE;
  const size_t fb = (size_t)f * NPIX + rowoff;

  h2 v[8];
#pragma unroll
  for (int q = 0; q < 8; q++) {
    int x = t + (q << 6);
    float2 xc = xh2[rowoff + x];
    float pr = __ldcs(pre + fb + x), pq = __ldcs(pim + fb + x);
    v[q] = __floats2half2_rn(xc.x * pr - xc.y * pq, xc.x * pq + xc.y * pr);
  }
  fft8h(v, PI2, MI2, CCh, NCC);
  h2* Sr = S + row * 576;
  Sr[t] = v[0];
#pragma unroll
  for (int r = 1; r < 8; r++)
    Sr[r * 72 + t] = ctwh(v[r], g_twh[t * r]);
  __syncthreads();

  const int r = t >> 3, T = t & 7;
#pragma unroll
  for (int q = 0; q < 8; q++)
    v[q] = Sr[r * 72 + T + (q << 3)];
  fft8h(v, PI2, MI2, CCh, NCC);
#pragma unroll
  for (int rp = 1; rp < 8; rp++)
    v[rp] = ctwh(v[rp], g_twh[8 * T * rp]);
  transpose8h(v, T);
  fft8h(v, PI2, MI2, CCh, NCC);
  __syncthreads();

#pragma unroll
  for (int k3 = 0; k3 < 8; k3++)
    S[((k3 << 6) + t) * 9 + row] = v[k3];
  __syncthreads();

  const size_t fxb = (size_t)f * NPIX;
  {
    int x = tid;
    uint4 lo = make_uint4(h2u(S[x*9+0]), h2u(S[x*9+1]), h2u(S[x*9+2]), h2u(S[x*9+3]));
    uint4 hi = make_uint4(h2u(S[x*9+4]), h2u(S[x*9+5]), h2u(S[x*9+6]), h2u(S[x*9+7]));
    uint4* dst = reinterpret_cast<uint4*>(g_tmp + fxb + (size_t)x * NSIDE + y0);
    dst[0] = lo; dst[1] = hi;
  }
}

// ---- stage 2: 512-pt IFFT along y (fp16 AoS, contiguous) + scaled modulus ----
// REVERSED filter order: consume most-recently-written g_tmp planes first (L2-hot).
__global__ void __launch_bounds__(256) cols_kernel() {
  __shared__ h2 S[4 * 576];
  __shared__ float red[8];
  DECL_H_CONSTS
  const int tid = threadIdx.x;
  const int cc = tid >> 6, t = tid & 63;
  const int f = NF - 1 - blockIdx.y;        // reverse order for L2 residency
  const int x = (blockIdx.x << 2) + cc;
  const size_t colbase = (size_t)f * NPIX + (size_t)x * NSIDE;

  h2 v[8];
#pragma unroll
  for (int q = 0; q < 8; q++)
    v[q] = g_tmp[colbase + t + (q << 6)];
  fft8h(v, PI2, MI2, CCh, NCC);
  h2* Sr = S + cc * 576;
  Sr[t] = v[0];
#pragma unroll
  for (int r = 1; r < 8; r++)
    Sr[r * 72 + t] = ctwh(v[r], g_twh[t * r]);
  __syncthreads();

  const int r = t >> 3, T = t & 7;
#pragma unroll
  for (int q = 0; q < 8; q++)
    v[q] = Sr[r * 72 + T + (q << 3)];
  fft8h(v, PI2, MI2, CCh, NCC);
#pragma unroll
  for (int rp = 1; rp < 8; rp++)
    v[rp] = ctwh(v[rp], g_twh[8 * T * rp]);
  transpose8h(v, T);
  fft8h(v, PI2, MI2, CCh, NCC);

  const float inv = 1.0f / (float)NPIX;
  float a2loc = 0.f;
#pragma unroll
  for (int k3 = 0; k3 < 8; k3++) {
    float2 a = __half22float2(v[k3]);
    float re = a.x * inv, im = a.y * inv;
    float h = sqrtf(re * re + im * im + 1e-8f) * 512.0f;
    if (f == 0) a2loc += h * h;
    g_m[colbase + (k3 << 6) + t] = __float2half_rn(h);
  }
  if (f == 0) {
    int lane = tid & 31, wp = tid >> 5;
    a2loc += __shfl_down_sync(0xffffffffu, a2loc, 16);
    a2loc += __shfl_down_sync(0xffffffffu, a2loc, 8);
    a2loc += __shfl_down_sync(0xffffffffu, a2loc, 4);
    a2loc += __shfl_down_sync(0xffffffffu, a2loc, 2);
    a2loc += __shfl_down_sync(0xffffffffu, a2loc, 1);
    if (lane == 0) red[wp] = a2loc;
    __syncthreads();
    if (tid == 0) {
      float s = 0.f;
#pragma unroll
      for (int w2 = 0; w2 < 8; w2++) s += red[w2];
      atomicAdd(&g_a2, s);
    }
  }
}

// ---- stage 3: all grams via HMMA, double-buffered pipeline ----
#define SB 1040

__device__ __forceinline__ void mma16816(float c[4], unsigned a0, unsigned a1, unsigned a2,
                                         unsigned a3, unsigned b0, unsigned b1) {
  asm volatile("mma.sync.aligned.m16n8k16.row.col.f32.f16.f16.f32 "
               "{%0,%1,%2,%3}, {%4,%5,%6,%7}, {%8,%9}, {%0,%1,%2,%3};"
               : "+f"(c[0]), "+f"(c[1]), "+f"(c[2]), "+f"(c[3])
               : "r"(a0), "r"(a1), "r"(a2), "r"(a3), "r"(b0), "r"(b1));
}

__global__ void __launch_bounds__(256) gram_kernel() {
  __shared__ __align__(16) unsigned char sm[2][24 * SB];
  const int g = blockIdx.x;
  const int tid = threadIdx.x;
  const int w = tid >> 5, lane = tid & 31;
  const bool jg = (g < 16);
  const size_t chunkbase = (size_t)blockIdx.y * 8192;

  for (int i = tid; i < 7 * 65; i += 256) {
    ((uint4*)(sm[0] + 17 * SB))[i] = make_uint4(0, 0, 0, 0);
    ((uint4*)(sm[1] + 17 * SB))[i] = make_uint4(0, 0, 0, 0);
  }

  const int ccc = tid & 63, rbase = tid >> 6;
  const uint4* src[5];
#pragma unroll
  for (int p = 0; p < 4; p++) {
    int rr = rbase + 4 * p;
    int fidx = jg ? (1 + rr * 16 + g) : (1 + (g - 16) * 16 + rr);
    src[p] = (const uint4*)(g_m + (size_t)fidx * NPIX) + ccc;
  }
  src[4] = (const uint4*)g_m + tid;
  const bool do_lp = jg && (tid < 64);

  float c0[4] = {0,0,0,0}, c1[4] = {0,0,0,0}, c2[4] = {0,0,0,0};

  unsigned smb[2] = { (unsigned)__cvta_generic_to_shared(sm[0]),
                      (unsigned)__cvta_generic_to_shared(sm[1]) };
  const unsigned arel = ((lane & 7) + ((lane >> 3) & 1) * 8) * SB + (lane >> 4) * 16;
  const unsigned lrel = (16 + (lane & 7)) * SB + ((lane >> 3) & 1) * 16;
  const unsigned pwarp = w * 128;
  const unsigned dst0 = rbase * SB + ccc * 16;

  uint4 rg[5];
  {
    const size_t P4 = chunkbase >> 3;
#pragma unroll
    for (int p = 0; p < 4; p++) rg[p] = src[p][P4];
    if (do_lp) rg[4] = src[4][P4];
#pragma unroll
    for (int p = 0; p < 4; p++)
      *(uint4*)(sm[0] + dst0 + p * 4 * SB) = rg[p];
    if (do_lp) *(uint4*)(sm[0] + 16 * SB + tid * 16) = rg[4];
  }
  __syncthreads();

  for (int it = 0; it < 16; it++) {
    const int b = it & 1;
    if (it < 15) {
      const size_t P4 = (chunkbase + (it + 1) * 512) >> 3;
#pragma unroll
      for (int p = 0; p < 4; p++) rg[p] = src[p][P4];
      if (do_lp) rg[4] = src[4][P4];
    }

#pragma unroll
    for (int ks = 0; ks < 4; ks++) {
      unsigned pb = pwarp + ks * 32;
      unsigned a0, a1, a2, a3;
      asm volatile("ldmatrix.sync.aligned.m8n8.x4.shared.b16 {%0,%1,%2,%3}, [%4];"
                   : "=r"(a0), "=r"(a1), "=r"(a2), "=r"(a3) : "r"(smb[b] + arel + pb));
      mma16816(c0, a0, a1, a2, a3, a0, a2);
      mma16816(c1, a0, a1, a2, a3, a1, a3);
      if (jg) {
        unsigned l0, l1;
        asm volatile("ldmatrix.sync.aligned.m8n8.x2.shared.b16 {%0,%1}, [%2];"
                     : "=r"(l0), "=r"(l1) : "r"(smb[b] + lrel + pb));
        mma16816(c2, a0, a1, a2, a3, l0, l1);
      }
    }

    if (it < 15) {
      unsigned char* dbuf = sm[1 - b];
#pragma unroll
      for (int p = 0; p < 4; p++)
        *(uint4*)(dbuf + dst0 + p * 4 * SB) = rg[p];
      if (do_lp) *(uint4*)(dbuf + 16 * SB + tid * 16) = rg[4];
    }
    __syncthreads();
  }

  float* Gs = (float*)sm;
  const int row0 = lane >> 2, colb = 2 * (lane & 3);
  float* W = Gs + w * 384;
  W[row0 * 24 + colb]            = c0[0];
  W[row0 * 24 + colb + 1]        = c0[1];
  W[(row0 + 8) * 24 + colb]      = c0[2];
  W[(row0 + 8) * 24 + colb + 1]  = c0[3];
  W[row0 * 24 + 8 + colb]        = c1[0];
  W[row0 * 24 + 8 + colb + 1]    = c1[1];
  W[(row0 + 8) * 24 + 8 + colb]     = c1[2];
  W[(row0 + 8) * 24 + 8 + colb + 1] = c1[3];
  W[row0 * 24 + 16 + colb]       = c2[0];
  W[row0 * 24 + 16 + colb + 1]   = c2[1];
  W[(row0 + 8) * 24 + 16 + colb]     = c2[2];
  W[(row0 + 8) * 24 + 16 + colb + 1] = c2[3];
  __syncthreads();
  for (int e = tid; e < 384; e += 256) {
    float s = 0.f;
#pragma unroll
    for (int w2 = 0; w2 < 8; w2++) s += Gs[w2 * 384 + e];
    atomicAdd(&g_gram[g * 384 + e], s);
  }
}

// ---- stage 4: assemble (reference ordering); scale 1/(NPIX*512^2) ----
__global__ void assemble_kernel(float* __restrict__ out) {
  const int t = threadIdx.x;
  const float inv = 1.0f / ((float)NPIX * 262144.0f);
  if (t == 0) out[0] = g_a2 * inv;
  if (t >= 256) return;
  int i = t >> 4, j = t & 15;
  int rowsum = 152 * i + 16 * (15 * i - (i * (i - 1)) / 2);
  int segsum = 2 * j + ((i < 15) ? (15 - i) * j : 0) + 15 * j - (j * (j - 1)) / 2;
  int pos = 1 + rowsum + segsum;
  const float* GA = g_gram + (j * 16 + i) * 24;
  out[pos++] = GA[i] * inv;
  out[pos++] = GA[16] * inv;
  if (i < 15)
    for (int l = i + 1; l < 16; l++)
      out[pos++] = g_gram[(j * 16 + i) * 24 + l] * inv;
  if (j < 15)
    for (int l = j + 1; l < 16; l++)
      out[pos++] = g_gram[((16 + i) * 16 + j) * 24 + l] * inv;
}

extern "C" void kernel_launch(void* const* d_in, const int* in_sizes, int n_in,
                              void* d_out, int out_size) {
  const float2* xh2 = (const float2*)d_in[0];
  const float* pre  = (const float*)d_in[1];
  const float* pim  = (const float*)d_in[2];
  float* out = (float*)d_out;

  init_kernel<<<1, 256>>>();
  rows_kernel<<<dim3(NSIDE / 8, NF), 512>>>(xh2, pre, pim);
  cols_kernel<<<dim3(NSIDE / 4, NF), 256>>>();
  gram_kernel<<<dim3(32, 32), 256>>>();
  assemble_kernel<<<1, 256>>>(out);
}

// round 15
// speedup vs baseline: 1.8636x; 1.0878x over previous
#include <cuda_runtime.h>
#include <cuda_fp16.h>
#include <math.h>

#define NSIDE 512
#define NPIX  (512*512)
#define NF    257

typedef __half2 h2;

// ---- scratch ----
__device__ __align__(16) h2     g_tmp[NF * NPIX];   // row-pass out, [f][x][y], complex fp16
__device__ __align__(16) __half g_m[NF * NPIX];     // modulus*512, [f][x][y], fp16
__device__ float g_gram[32 * 16 * 24];
__device__ float g_a2;
__device__ uint2 g_twh[512];                        // fp16 twiddles {(c,c),(-s,s)}

__device__ __forceinline__ unsigned h2u(h2 a){ return *reinterpret_cast<unsigned*>(&a); }
__device__ __forceinline__ h2 u2h(unsigned a){ return *reinterpret_cast<h2*>(&a); }
__device__ __forceinline__ h2 hswap(h2 a){ return __lowhigh2highlow(a); }

#define DECL_H_CONSTS \
  const h2 PI2 = __floats2half2_rn(-1.f, 1.f); \
  const h2 MI2 = __floats2half2_rn(1.f, -1.f); \
  const h2 CCh = __floats2half2_rn(0.70710678118654752440f, 0.70710678118654752440f); \
  const h2 NCC = __floats2half2_rn(-0.70710678118654752440f, 0.70710678118654752440f);

// 8-pt DFT, +i sign, natural order, fp16 AoS complex (one h2 = one complex)
__device__ __forceinline__ void fft8h(h2 v[8], h2 PI2, h2 MI2, h2 CCh, h2 NCC) {
  h2 es0 = __hadd2(v[0], v[4]), ed0 = __hsub2(v[0], v[4]);
  h2 es1 = __hadd2(v[2], v[6]), ed1 = __hsub2(v[2], v[6]);
  h2 E0 = __hadd2(es0, es1), E2 = __hsub2(es0, es1);
  h2 sd1 = hswap(ed1);
  h2 E1 = __hfma2(sd1, PI2, ed0);
  h2 E3 = __hfma2(sd1, MI2, ed0);
  h2 os0 = __hadd2(v[1], v[5]), od0 = __hsub2(v[1], v[5]);
  h2 os1 = __hadd2(v[3], v[7]), od1 = __hsub2(v[3], v[7]);
  h2 O0 = __hadd2(os0, os1), O2 = __hsub2(os0, os1);
  h2 sod = hswap(od1);
  h2 O1 = __hfma2(sod, PI2, od0);
  h2 O3 = __hfma2(sod, MI2, od0);
  h2 t1 = __hfma2(hswap(O1), PI2, O1);
  h2 O1t = __hmul2(t1, CCh);
  h2 O2t = __hmul2(hswap(O2), PI2);
  h2 t2 = __hfma2(hswap(O3), PI2, O3);
  h2 O3t = __hmul2(hswap(t2), NCC);
  v[0] = __hadd2(E0, O0);  v[4] = __hsub2(E0, O0);
  v[1] = __hadd2(E1, O1t); v[5] = __hsub2(E1, O1t);
  v[2] = __hadd2(E2, O2t); v[6] = __hsub2(E2, O2t);
  v[3] = __hadd2(E3, O3t); v[7] = __hsub2(E3, O3t);
}

__device__ __forceinline__ h2 ctwh(h2 a, uint2 w) {   // a * (c + i s)
  return __hfma2(hswap(a), u2h(w.y), __hmul2(a, u2h(w.x)));
}

// 8x8 transpose among 8 lanes differing in low-3 lane bits (32-bit shuffles)
__device__ __forceinline__ void transpose8h(h2 v[8], int f3) {
#pragma unroll
  for (int mb = 0; mb < 3; mb++) {
    const int m = 1 << mb;
#pragma unroll
    for (int i = 0; i < 8; i++) {
      if ((i & m) == 0) {
        const int ip = i | m;
        const bool hi = (f3 & m) != 0;
        unsigned send = h2u(hi ? v[i] : v[ip]);
        unsigned got = __shfl_xor_sync(0xffffffffu, send, m);
        if (hi) v[i] = u2h(got); else v[ip] = u2h(got);
      }
    }
  }
}

__global__ void init_kernel() {
  int t = threadIdx.x;
  for (int m = t; m < 512; m += 256) {
    float s, c;
    sincospif((float)m * (1.0f / 256.0f), &s, &c);
    h2 wc = __floats2half2_rn(c, c), ws = __floats2half2_rn(-s, s);
    g_twh[m] = make_uint2(h2u(wc), h2u(ws));
  }
  for (int i = t; i < 32 * 384; i += 256) g_gram[i] = 0.f;
  if (t == 0) g_a2 = 0.f;
}

// ---- stage 1: product + 512-pt IFFT along x (fp16 AoS); transposed store [f][x][y] ----
// Store stage remapped: 8 lanes cooperate per x -> 4 lines per STG.32 (was 32 per STG.128).
__global__ void __launch_bounds__(512) rows_kernel(const float2* __restrict__ xh2,
                                                   const float* __restrict__ pre,
                                                   const float* __restrict__ pim) {
  __shared__ h2 S[5120];   // 20 KB: FFT stage 8*576; transpose stage stride 9
  DECL_H_CONSTS
  const int tid = threadIdx.x;
  const int row = tid >> 6, t = tid & 63;
  const int f = blockIdx.y;
  const int y0 = blockIdx.x << 3;
  const size_t rowoff = (size_t)(y0 + row) * NSIDE;
  const size_t fb = (size_t)f * NPIX + rowoff;

  h2 v[8];
#pragma unroll
  for (int q = 0; q < 8; q++) {
    int x = t + (q << 6);
    float2 xc = xh2[rowoff + x];
    float pr = __ldcs(pre + fb + x), pq = __ldcs(pim + fb + x);
    v[q] = __floats2half2_rn(xc.x * pr - xc.y * pq, xc.x * pq + xc.y * pr);
  }
  fft8h(v, PI2, MI2, CCh, NCC);
  h2* Sr = S + row * 576;
  Sr[t] = v[0];
#pragma unroll
  for (int r = 1; r < 8; r++)
    Sr[r * 72 + t] = ctwh(v[r], g_twh[t * r]);
  __syncthreads();

  const int r = t >> 3, T = t & 7;
#pragma unroll
  for (int q = 0; q < 8; q++)
    v[q] = Sr[r * 72 + T + (q << 3)];
  fft8h(v, PI2, MI2, CCh, NCC);
#pragma unroll
  for (int rp = 1; rp < 8; rp++)
    v[rp] = ctwh(v[rp], g_twh[8 * T * rp]);
  transpose8h(v, T);
  fft8h(v, PI2, MI2, CCh, NCC);
  __syncthreads();

#pragma unroll
  for (int k3 = 0; k3 < 8; k3++)
    S[((k3 << 6) + t) * 9 + row] = v[k3];
  __syncthreads();

  // cooperative store: lane group of 8 per x, 4 lines per STG.32
  const size_t fxb = (size_t)f * NPIX;
  const int xi = tid >> 3, c = tid & 7;
#pragma unroll
  for (int k = 0; k < 8; k++) {
    int x = xi + (k << 6);
    ((unsigned*)(g_tmp + fxb + (size_t)x * NSIDE + y0))[c] = h2u(S[x * 9 + c]);
  }
}

// ---- stage 2: 512-pt IFFT along y (fp16 AoS, contiguous) + scaled modulus ----
__global__ void __launch_bounds__(256) cols_kernel() {
  __shared__ h2 S[4 * 576];
  __shared__ float red[8];
  DECL_H_CONSTS
  const int tid = threadIdx.x;
  const int cc = tid >> 6, t = tid & 63;
  const int f = NF - 1 - blockIdx.y;
  const int x = (blockIdx.x << 2) + cc;
  const size_t colbase = (size_t)f * NPIX + (size_t)x * NSIDE;

  h2 v[8];
#pragma unroll
  for (int q = 0; q < 8; q++)
    v[q] = g_tmp[colbase + t + (q << 6)];
  fft8h(v, PI2, MI2, CCh, NCC);
  h2* Sr = S + cc * 576;
  Sr[t] = v[0];
#pragma unroll
  for (int r = 1; r < 8; r++)
    Sr[r * 72 + t] = ctwh(v[r], g_twh[t * r]);
  __syncthreads();

  const int r = t >> 3, T = t & 7;
#pragma unroll
  for (int q = 0; q < 8; q++)
    v[q] = Sr[r * 72 + T + (q << 3)];
  fft8h(v, PI2, MI2, CCh, NCC);
#pragma unroll
  for (int rp = 1; rp < 8; rp++)
    v[rp] = ctwh(v[rp], g_twh[8 * T * rp]);
  transpose8h(v, T);
  fft8h(v, PI2, MI2, CCh, NCC);

  const float inv = 1.0f / (float)NPIX;
  float a2loc = 0.f;
#pragma unroll
  for (int k3 = 0; k3 < 8; k3++) {
    float2 a = __half22float2(v[k3]);
    float re = a.x * inv, im = a.y * inv;
    float h = sqrtf(re * re + im * im + 1e-8f) * 512.0f;
    if (f == 0) a2loc += h * h;
    g_m[colbase + (k3 << 6) + t] = __float2half_rn(h);
  }
  if (f == 0) {
    int lane = tid & 31, wp = tid >> 5;
    a2loc += __shfl_down_sync(0xffffffffu, a2loc, 16);
    a2loc += __shfl_down_sync(0xffffffffu, a2loc, 8);
    a2loc += __shfl_down_sync(0xffffffffu, a2loc, 4);
    a2loc += __shfl_down_sync(0xffffffffu, a2loc, 2);
    a2loc += __shfl_down_sync(0xffffffffu, a2loc, 1);
    if (lane == 0) red[wp] = a2loc;
    __syncthreads();
    if (tid == 0) {
      float s = 0.f;
#pragma unroll
      for (int w2 = 0; w2 < 8; w2++) s += red[w2];
      atomicAdd(&g_a2, s);
    }
  }
}

// ---- stage 3: all grams via HMMA, double-buffered pipeline ----
#define SB 1040

__device__ __forceinline__ void mma16816(float c[4], unsigned a0, unsigned a1, unsigned a2,
                                         unsigned a3, unsigned b0, unsigned b1) {
  asm volatile("mma.sync.aligned.m16n8k16.row.col.f32.f16.f16.f32 "
               "{%0,%1,%2,%3}, {%4,%5,%6,%7}, {%8,%9}, {%0,%1,%2,%3};"
               : "+f"(c[0]), "+f"(c[1]), "+f"(c[2]), "+f"(c[3])
               : "r"(a0), "r"(a1), "r"(a2), "r"(a3), "r"(b0), "r"(b1));
}

__global__ void __launch_bounds__(256) gram_kernel() {
  __shared__ __align__(16) unsigned char sm[2][24 * SB];
  const int g = blockIdx.x;
  const int tid = threadIdx.x;
  const int w = tid >> 5, lane = tid & 31;
  const bool jg = (g < 16);
  const size_t chunkbase = (size_t)blockIdx.y * 8192;

  for (int i = tid; i < 7 * 65; i += 256) {
    ((uint4*)(sm[0] + 17 * SB))[i] = make_uint4(0, 0, 0, 0);
    ((uint4*)(sm[1] + 17 * SB))[i] = make_uint4(0, 0, 0, 0);
  }

  const int ccc = tid & 63, rbase = tid >> 6;
  const uint4* src[5];
#pragma unroll
  for (int p = 0; p < 4; p++) {
    int rr = rbase + 4 * p;
    int fidx = jg ? (1 + rr * 16 + g) : (1 + (g - 16) * 16 + rr);
    src[p] = (const uint4*)(g_m + (size_t)fidx * NPIX) + ccc;
  }
  src[4] = (const uint4*)g_m + tid;
  const bool do_lp = jg && (tid < 64);

  float c0[4] = {0,0,0,0}, c1[4] = {0,0,0,0}, c2[4] = {0,0,0,0};

  unsigned smb[2] = { (unsigned)__cvta_generic_to_shared(sm[0]),
                      (unsigned)__cvta_generic_to_shared(sm[1]) };
  const unsigned arel = ((lane & 7) + ((lane >> 3) & 1) * 8) * SB + (lane >> 4) * 16;
  const unsigned lrel = (16 + (lane & 7)) * SB + ((lane >> 3) & 1) * 16;
  const unsigned pwarp = w * 128;
  const unsigned dst0 = rbase * SB + ccc * 16;

  uint4 rg[5];
  {
    const size_t P4 = chunkbase >> 3;
#pragma unroll
    for (int p = 0; p < 4; p++) rg[p] = src[p][P4];
    if (do_lp) rg[4] = src[4][P4];
#pragma unroll
    for (int p = 0; p < 4; p++)
      *(uint4*)(sm[0] + dst0 + p * 4 * SB) = rg[p];
    if (do_lp) *(uint4*)(sm[0] + 16 * SB + tid * 16) = rg[4];
  }
  __syncthreads();

  for (int it = 0; it < 16; it++) {
    const int b = it & 1;
    if (it < 15) {
      const size_t P4 = (chunkbase + (it + 1) * 512) >> 3;
#pragma unroll
      for (int p = 0; p < 4; p++) rg[p] = src[p][P4];
      if (do_lp) rg[4] = src[4][P4];
    }

#pragma unroll
    for (int ks = 0; ks < 4; ks++) {
      unsigned pb = pwarp + ks * 32;
      unsigned a0, a1, a2, a3;
      asm volatile("ldmatrix.sync.aligned.m8n8.x4.shared.b16 {%0,%1,%2,%3}, [%4];"
                   : "=r"(a0), "=r"(a1), "=r"(a2), "=r"(a3) : "r"(smb[b] + arel + pb));
      mma16816(c0, a0, a1, a2, a3, a0, a2);
      mma16816(c1, a0, a1, a2, a3, a1, a3);
      if (jg) {
        unsigned l0, l1;
        asm volatile("ldmatrix.sync.aligned.m8n8.x2.shared.b16 {%0,%1}, [%2];"
                     : "=r"(l0), "=r"(l1) : "r"(smb[b] + lrel + pb));
        mma16816(c2, a0, a1, a2, a3, l0, l1);
      }
    }

    if (it < 15) {
      unsigned char* dbuf = sm[1 - b];
#pragma unroll
      for (int p = 0; p < 4; p++)
        *(uint4*)(dbuf + dst0 + p * 4 * SB) = rg[p];
      if (do_lp) *(uint4*)(dbuf + 16 * SB + tid * 16) = rg[4];
    }
    __syncthreads();
  }

  float* Gs = (float*)sm;
  const int row0 = lane >> 2, colb = 2 * (lane & 3);
  float* W = Gs + w * 384;
  W[row0 * 24 + colb]            = c0[0];
  W[row0 * 24 + colb + 1]        = c0[1];
  W[(row0 + 8) * 24 + colb]      = c0[2];
  W[(row0 + 8) * 24 + colb + 1]  = c0[3];
  W[row0 * 24 + 8 + colb]        = c1[0];
  W[row0 * 24 + 8 + colb + 1]    = c1[1];
  W[(row0 + 8) * 24 + 8 + colb]     = c1[2];
  W[(row0 + 8) * 24 + 8 + colb + 1] = c1[3];
  W[row0 * 24 + 16 + colb]       = c2[0];
  W[row0 * 24 + 16 + colb + 1]   = c2[1];
  W[(row0 + 8) * 24 + 16 + colb]     = c2[2];
  W[(row0 + 8) * 24 + 16 + colb + 1] = c2[3];
  __syncthreads();
  for (int e = tid; e < 384; e += 256) {
    float s = 0.f;
#pragma unroll
    for (int w2 = 0; w2 < 8; w2++) s += Gs[w2 * 384 + e];
    atomicAdd(&g_gram[g * 384 + e], s);
  }
}

// ---- stage 4: assemble (reference ordering); scale 1/(NPIX*512^2) ----
__global__ void assemble_kernel(float* __restrict__ out) {
  const int t = threadIdx.x;
  const float inv = 1.0f / ((float)NPIX * 262144.0f);
  if (t == 0) out[0] = g_a2 * inv;
  if (t >= 256) return;
  int i = t >> 4, j = t & 15;
  int rowsum = 152 * i + 16 * (15 * i - (i * (i - 1)) / 2);
  int segsum = 2 * j + ((i < 15) ? (15 - i) * j : 0) + 15 * j - (j * (j - 1)) / 2;
  int pos = 1 + rowsum + segsum;
  const float* GA = g_gram + (j * 16 + i) * 24;
  out[pos++] = GA[i] * inv;
  out[pos++] = GA[16] * inv;
  if (i < 15)
    for (int l = i + 1; l < 16; l++)
      out[pos++] = g_gram[(j * 16 + i) * 24 + l] * inv;
  if (j < 15)
    for (int l = j + 1; l < 16; l++)
      out[pos++] = g_gram[((16 + i) * 16 + j) * 24 + l] * inv;
}

extern "C" void kernel_launch(void* const* d_in, const int* in_sizes, int n_in,
                              void* d_out, int out_size) {
  const float2* xh2 = (const float2*)d_in[0];
  const float* pre  = (const float*)d_in[1];
  const float* pim  = (const float*)d_in[2];
  float* out = (float*)d_out;

  init_kernel<<<1, 256>>>();
  rows_kernel<<<dim3(NSIDE / 8, NF), 512>>>(xh2, pre, pim);
  cols_kernel<<<dim3(NSIDE / 4, NF), 256>>>();
  gram_kernel<<<dim3(32, 32), 256>>>();
  assemble_kernel<<<1, 256>>>(out);
}